// round 11
// baseline (speedup 1.0000x reference)
#include <cuda_runtime.h>
#include <cuda_fp16.h>
#include <cstdint>

#define NN 100000
#define NE 1600000
#define D  128
#define NPAD (NN + 128)

typedef unsigned int u32;
typedef unsigned long long u64;

// ---- scratch (static device globals; allocation-free) ----
__device__ int    g_rowptr[NN + 1];
__device__ int    g_cursor[NN];
__device__ int    g_col[NE];
__device__ u64    g_bstate[128];
__device__ __align__(16) __half g_hh[(size_t)NPAD * D];   // h (fp16)
__device__ __align__(16) __half g_yl[(size_t)NPAD * D];   // A@W_l (fp16)
__device__ __align__(16) __half g_z [(size_t)NPAD * D];   // A@W_r + b (fp16)
__device__ __align__(16) u32 g_B[4][64 * 128];            // fp16 weights k-pair packed

// ---------------- helpers ----------------
__device__ __forceinline__ u32 pack2(__half a, __half b) {
    __half2 h = __halves2half2(a, b);
    return *(u32*)&h;
}
__device__ __forceinline__ void mma16816(float* c, const u32* a, const u32* b) {
    asm volatile(
        "mma.sync.aligned.m16n8k16.row.col.f32.f16.f16.f32 "
        "{%0,%1,%2,%3}, {%4,%5,%6,%7}, {%8,%9}, {%0,%1,%2,%3};"
        : "+f"(c[0]), "+f"(c[1]), "+f"(c[2]), "+f"(c[3])
        : "r"(a[0]), "r"(a[1]), "r"(a[2]), "r"(a[3]), "r"(b[0]), "r"(b[1]));
}
#define CP_ASYNC8(sm, gp) \
    asm volatile("cp.async.ca.shared.global [%0], [%1], 8;" :: "r"(sm), "l"(gp))
#define CP_COMMIT() asm volatile("cp.async.commit_group;")
#define CP_WAIT1()  asm volatile("cp.async.wait_group 1;")
#define CP_WAIT0()  asm volatile("cp.async.wait_group 0;")

// ---------------- CSR build ----------------
__global__ void k_zero(int n) {
    int i = blockIdx.x * blockDim.x + threadIdx.x;
    if (i < 128) g_bstate[i] = 0ULL;
    if (i < n) g_cursor[i] = 0;
}
__global__ void k_hist(const int* __restrict__ dst, int e4) {
    int i = blockIdx.x * blockDim.x + threadIdx.x;
    if (i >= e4) return;
    int4 d = ((const int4*)dst)[i];
    atomicAdd(&g_cursor[d.x], 1);
    atomicAdd(&g_cursor[d.y], 1);
    atomicAdd(&g_cursor[d.z], 1);
    atomicAdd(&g_cursor[d.w], 1);
}
// single-pass decoupled-lookback scan: counts -> rowptr/cursor (exclusive)
__global__ void k_scanLB(int n, int e) {
    __shared__ int sh[1024];
    __shared__ int s_T;
    __shared__ int s_prefix;
    int bid = blockIdx.x, t = threadIdx.x;
    int i = bid * 1024 + t;
    int v = (i < n) ? g_cursor[i] : 0;
    sh[t] = v;
    __syncthreads();
    for (int off = 1; off < 1024; off <<= 1) {
        int w = (t >= off) ? sh[t - off] : 0;
        __syncthreads();
        sh[t] += w;
        __syncthreads();
    }
    if (t == 1023) s_T = sh[1023];
    if (t == 0 && bid == 0) s_prefix = 0;
    __syncthreads();
    int T = s_T;

    if (t == 0) {
        u64 st = ((u64)(unsigned)T << 32) | (bid == 0 ? 2ULL : 1ULL);
        atomicExch(&g_bstate[bid], st);
    }
    if (t < 32 && bid > 0) {
        int lane = t;
        int prefix = 0;
        int base = bid - 1;
        while (true) {
            int j = base - lane;
            u64 s = (j >= 0) ? *(volatile u64*)&g_bstate[j] : 2ULL;
            unsigned f = (unsigned)(s & 3ULL);
            if (__all_sync(0xFFFFFFFFu, f != 0u)) {
                int val = (int)(unsigned)(s >> 32);
                unsigned pm = __ballot_sync(0xFFFFFFFFu, f == 2u);
                if (pm) {
                    int fp = __ffs(pm) - 1;
                    int xx = (lane <= fp) ? val : 0;
                    #pragma unroll
                    for (int o = 16; o; o >>= 1) xx += __shfl_xor_sync(0xFFFFFFFFu, xx, o);
                    prefix += xx;
                    break;
                } else {
                    int xx = val;
                    #pragma unroll
                    for (int o = 16; o; o >>= 1) xx += __shfl_xor_sync(0xFFFFFFFFu, xx, o);
                    prefix += xx;
                    base -= 32;
                }
            }
        }
        if (lane == 0) {
            atomicExch(&g_bstate[bid], ((u64)(unsigned)(prefix + T) << 32) | 2ULL);
            s_prefix = prefix;
        }
    }
    __syncthreads();
    int r = s_prefix + sh[t] - v;
    if (i < n) {
        g_rowptr[i] = r;
        g_cursor[i] = r;
    }
    if (bid == 0 && t == 0) g_rowptr[n] = e;
}
__global__ void k_scatter(const int* __restrict__ src, const int* __restrict__ dst, int e4) {
    int i = blockIdx.x * blockDim.x + threadIdx.x;
    if (i >= e4) return;
    int4 s = ((const int4*)src)[i];
    int4 d = ((const int4*)dst)[i];
    int p0 = atomicAdd(&g_cursor[d.x], 1); g_col[p0] = s.x;
    int p1 = atomicAdd(&g_cursor[d.y], 1); g_col[p1] = s.y;
    int p2 = atomicAdd(&g_cursor[d.z], 1); g_col[p2] = s.z;
    int p3 = atomicAdd(&g_cursor[d.w], 1); g_col[p3] = s.w;
}

// ---------------- weight prep: fp32 W[k][n] -> fp16 k-pair-packed [kp][n] ----------------
__global__ void k_prepB(const float* __restrict__ W0, const float* __restrict__ W1,
                        const float* __restrict__ W2, const float* __restrict__ W3) {
    const float* Ws[4] = {W0, W1, W2, W3};
    const float* W = Ws[blockIdx.x];
    u32* b = g_B[blockIdx.x];
    for (int u = threadIdx.x; u < 64 * 128; u += blockDim.x) {
        int kp = u >> 7, n = u & 127;
        b[u] = pack2(__float2half_rn(W[(2 * kp) * D + n]),
                     __float2half_rn(W[(2 * kp + 1) * D + n]));
    }
}

// ---------------- HMMA cat-GEMM: [yl | z] = A @ [Bl | Br] (+bias on z) ----------------
#define AS 68
#define BS 264
#define SM_U32_TOTAL (128 * AS + 64 * BS)

__global__ __launch_bounds__(256, 1) void k_gemm(
    const float* __restrict__ A32, const __half* __restrict__ A16, int a32,
    const u32* __restrict__ Bg0, const u32* __restrict__ Bg1,
    const float* __restrict__ bias,
    __half* __restrict__ yl, __half* __restrict__ z, int M)
{
    extern __shared__ __align__(16) u32 sm[];
    u32* Asm = sm;
    u32* Bsm = sm + 128 * AS;

    int tid = threadIdx.x, wid = tid >> 5, lane = tid & 31;
    int g = lane >> 2, tg = lane & 3;
    int wm = (wid & 1) * 64, wn = (wid >> 1) * 64;
    int m0 = blockIdx.x * 128;

    for (int u = tid; u < 2048; u += 256) {
        int r = u >> 5, c4 = u & 31;
        *(uint4*)&Bsm[r * BS + c4 * 4]       = ((const uint4*)Bg0)[u];
        *(uint4*)&Bsm[r * BS + 128 + c4 * 4] = ((const uint4*)Bg1)[u];
    }
    if (a32) {
        for (int u = tid; u < 2048; u += 256) {
            int r = u >> 4, c4 = u & 15;
            int gr = m0 + r;
            float4 fa = make_float4(0.f, 0.f, 0.f, 0.f), fb = fa;
            if (gr < M) {
                const float4* p = (const float4*)(A32 + (size_t)gr * D + c4 * 8);
                fa = p[0]; fb = p[1];
            }
            *(uint4*)&Asm[r * AS + c4 * 4] = make_uint4(
                pack2(__float2half_rn(fa.x), __float2half_rn(fa.y)),
                pack2(__float2half_rn(fa.z), __float2half_rn(fa.w)),
                pack2(__float2half_rn(fb.x), __float2half_rn(fb.y)),
                pack2(__float2half_rn(fb.z), __float2half_rn(fb.w)));
        }
    } else {
        const u32* Ag = (const u32*)A16;
        for (int u = tid; u < 2048; u += 256) {
            int r = u >> 4, c4 = u & 15;
            *(uint4*)&Asm[r * AS + c4 * 4] =
                *(const uint4*)(Ag + (size_t)(m0 + r) * 64 + c4 * 4);
        }
    }
    __syncthreads();

    float acc[4][8][4];
    #pragma unroll
    for (int mt = 0; mt < 4; ++mt)
        #pragma unroll
        for (int nt = 0; nt < 8; ++nt)
            #pragma unroll
            for (int c = 0; c < 4; ++c) acc[mt][nt][c] = 0.f;

    #pragma unroll
    for (int ks = 0; ks < 8; ++ks) {
        u32 afr[4][4];
        #pragma unroll
        for (int mt = 0; mt < 4; ++mt) {
            int r = wm + mt * 16 + g;
            afr[mt][0] = Asm[r * AS + ks * 8 + tg];
            afr[mt][1] = Asm[(r + 8) * AS + ks * 8 + tg];
            afr[mt][2] = Asm[r * AS + ks * 8 + tg + 4];
            afr[mt][3] = Asm[(r + 8) * AS + ks * 8 + tg + 4];
        }
        u32 bfr[8][2];
        #pragma unroll
        for (int nt = 0; nt < 8; ++nt) {
            int n = wn + nt * 8 + g;
            bfr[nt][0] = Bsm[(ks * 8 + tg) * BS + n];
            bfr[nt][1] = Bsm[(ks * 8 + tg + 4) * BS + n];
        }
        #pragma unroll
        for (int mt = 0; mt < 4; ++mt)
            #pragma unroll
            for (int nt = 0; nt < 8; ++nt)
                mma16816(acc[mt][nt], afr[mt], bfr[nt]);
    }

    #pragma unroll
    for (int nt = 0; nt < 8; ++nt) {
        int ccol = wn + nt * 8 + tg * 2;
        if (ccol < 128) {
            #pragma unroll
            for (int mt = 0; mt < 4; ++mt) {
                int r0 = m0 + wm + mt * 16 + g;
                *(__half2*)(yl + (size_t)r0 * D + ccol) =
                    __floats2half2_rn(acc[mt][nt][0], acc[mt][nt][1]);
                *(__half2*)(yl + (size_t)(r0 + 8) * D + ccol) =
                    __floats2half2_rn(acc[mt][nt][2], acc[mt][nt][3]);
            }
        } else {
            int zc = ccol - 128;
            float bv0 = __ldg(bias + zc), bv1 = __ldg(bias + zc + 1);
            #pragma unroll
            for (int mt = 0; mt < 4; ++mt) {
                int r0 = m0 + wm + mt * 16 + g;
                *(__half2*)(z + (size_t)r0 * D + zc) =
                    __floats2half2_rn(acc[mt][nt][0] + bv0, acc[mt][nt][1] + bv1);
                *(__half2*)(z + (size_t)(r0 + 8) * D + zc) =
                    __floats2half2_rn(acc[mt][nt][2] + bv0, acc[mt][nt][3] + bv1);
            }
        }
    }
}

// ---------------- fused mean-agg + add-self + (relu) ----------------
// warp per node; cp.async double-buffered smem pipeline: issue batch k+1
// while accumulating batch k from shared. No register staging, continuous
// load issue. Accumulation order identical to the direct-LDG version.
__global__ __launch_bounds__(256) void k_aggf(
    const __half* __restrict__ yl, const __half* __restrict__ z,
    __half* __restrict__ outh, float* __restrict__ outf,
    int relu, int n)
{
    __shared__ __align__(16) unsigned char sbuf[8][2][8 * 256];  // 32 KB
    int wiw  = threadIdx.x >> 5;
    int w    = (blockIdx.x * blockDim.x + threadIdx.x) >> 5;
    int lane = threadIdx.x & 31;
    if (w >= n) return;
    int beg = g_rowptr[w], end = g_rowptr[w + 1];
    float a0 = 0.f, a1 = 0.f, a2 = 0.f, a3 = 0.f;
    int deg = end - beg;
    int nb = deg >> 3;                       // full 8-edge batches

    unsigned char* b0 = sbuf[wiw][0];
    unsigned char* b1 = sbuf[wiw][1];
    u32 sb0 = (u32)__cvta_generic_to_shared(b0) + lane * 8;
    u32 sb1 = (u32)__cvta_generic_to_shared(b1) + lane * 8;

    if (nb > 0) {
        // issue batch 0 into buffer 0
        #pragma unroll
        for (int r = 0; r < 8; ++r) {
            int c = g_col[beg + r];
            CP_ASYNC8(sb0 + r * 256, (const char*)yl + (size_t)c * 256 + lane * 8);
        }
        CP_COMMIT();
        for (int b = 1; b < nb; ++b) {
            u32 sbi = (b & 1) ? sb1 : sb0;
            int jb = beg + b * 8;
            #pragma unroll
            for (int r = 0; r < 8; ++r) {
                int c = g_col[jb + r];
                CP_ASYNC8(sbi + r * 256, (const char*)yl + (size_t)c * 256 + lane * 8);
            }
            CP_COMMIT();
            CP_WAIT1();                       // batch b-1 resident
            unsigned char* bp = ((b - 1) & 1) ? b1 : b0;
            #pragma unroll
            for (int r = 0; r < 8; ++r) {
                uint2 u = *(const uint2*)(bp + r * 256 + lane * 8);
                float2 f0 = __half22float2(*(__half2*)&u.x);
                float2 f1 = __half22float2(*(__half2*)&u.y);
                a0 += f0.x; a1 += f0.y; a2 += f1.x; a3 += f1.y;
            }
        }
        CP_WAIT0();                           // last batch resident
        unsigned char* bp = ((nb - 1) & 1) ? b1 : b0;
        #pragma unroll
        for (int r = 0; r < 8; ++r) {
            uint2 u = *(const uint2*)(bp + r * 256 + lane * 8);
            float2 f0 = __half22float2(*(__half2*)&u.x);
            float2 f1 = __half22float2(*(__half2*)&u.y);
            a0 += f0.x; a1 += f0.y; a2 += f1.x; a3 += f1.y;
        }
    }
    for (int j = beg + nb * 8; j < end; ++j) {
        int s = g_col[j];
        uint2 u = *((const uint2*)(yl + (size_t)s * D) + lane);
        float2 f0 = __half22float2(*(__half2*)&u.x);
        float2 f1 = __half22float2(*(__half2*)&u.y);
        a0 += f0.x; a1 += f0.y; a2 += f1.x; a3 += f1.y;
    }

    float inv = 1.0f / (float)(deg > 1 ? deg : 1);
    uint2 zu = *((const uint2*)(z + (size_t)w * D) + lane);
    float2 z0 = __half22float2(*(__half2*)&zu.x);
    float2 z1 = __half22float2(*(__half2*)&zu.y);
    float v0 = a0 * inv + z0.x, v1 = a1 * inv + z0.y;
    float v2 = a2 * inv + z1.x, v3 = a3 * inv + z1.y;
    if (relu) {
        v0 = v0 > 0.f ? v0 : 0.f; v1 = v1 > 0.f ? v1 : 0.f;
        v2 = v2 > 0.f ? v2 : 0.f; v3 = v3 > 0.f ? v3 : 0.f;
    }
    if (outh) {
        *((uint2*)(outh + (size_t)w * D) + lane) =
            make_uint2(pack2(__float2half_rn(v0), __float2half_rn(v1)),
                       pack2(__float2half_rn(v2), __float2half_rn(v3)));
    } else {
        *((float4*)(outf + (size_t)w * D) + lane) = make_float4(v0, v1, v2, v3);
    }
}

// ---------------- launch ----------------
extern "C" void kernel_launch(void* const* d_in, const int* in_sizes, int n_in,
                              void* d_out, int out_size)
{
    const float* x   = (const float*)d_in[0];
    const int*   ei  = (const int*)d_in[1];
    const float* W1l = (const float*)d_in[2];
    const float* b1  = (const float*)d_in[3];
    const float* W1r = (const float*)d_in[4];
    const float* W2l = (const float*)d_in[5];
    const float* b2  = (const float*)d_in[6];
    const float* W2r = (const float*)d_in[7];
    float* out = (float*)d_out;

    int N = in_sizes[0] / D;
    int E = in_sizes[1] / 2;
    const int* src = ei;
    const int* dst = ei + E;

    __half *hh, *yl, *z;
    u32 *B0, *B1, *B2, *B3;
    cudaGetSymbolAddress((void**)&hh, g_hh);
    cudaGetSymbolAddress((void**)&yl, g_yl);
    cudaGetSymbolAddress((void**)&z,  g_z);
    {
        u32* bb;
        cudaGetSymbolAddress((void**)&bb, g_B);
        B0 = bb; B1 = bb + 8192; B2 = bb + 16384; B3 = bb + 24576;
    }

    cudaFuncSetAttribute(k_gemm, cudaFuncAttributeMaxDynamicSharedMemorySize,
                         SM_U32_TOTAL * 4);

    static cudaStream_t sB = nullptr;
    static cudaEvent_t evFork = nullptr, evJoin = nullptr;
    if (!sB) {
        cudaStreamCreateWithFlags(&sB, cudaStreamNonBlocking);
        cudaEventCreateWithFlags(&evFork, cudaEventDisableTiming);
        cudaEventCreateWithFlags(&evJoin, cudaEventDisableTiming);
    }

    int e4 = (E + 3) / 4;
    int nb = (N + 1023) / 1024;
    int aggBlocks  = (N * 32 + 255) / 256;
    int gemmBlocks = (N + 127) / 128;

    // fork: CSR build on side stream
    cudaEventRecord(evFork, 0);
    cudaStreamWaitEvent(sB, evFork, 0);
    k_zero   <<<(N + 255) / 256, 256, 0, sB>>>(N);
    k_hist   <<<(e4 + 255) / 256, 256, 0, sB>>>(dst, e4);
    k_scanLB <<<nb, 1024, 0, sB>>>(N, E);
    k_scatter<<<(e4 + 255) / 256, 256, 0, sB>>>(src, dst, e4);
    cudaEventRecord(evJoin, sB);

    // main stream: weights + layer-1 GEMM (reads fp32 x directly)
    k_prepB<<<4, 256>>>(W1l, W1r, W2l, W2r);
    k_gemm <<<gemmBlocks, 256, SM_U32_TOTAL * 4>>>(
        x, nullptr, 1, B0, B1, b1, yl, z, N);

    // join, then agg/gemm/agg
    cudaStreamWaitEvent(0, evJoin, 0);
    k_aggf<<<aggBlocks, 256>>>(yl, z, hh, nullptr, 1, N);
    k_gemm<<<gemmBlocks, 256, SM_U32_TOTAL * 4>>>(
        nullptr, hh, 0, B2, B3, b2, yl, z, N);
    k_aggf<<<aggBlocks, 256>>>(yl, z, nullptr, out, 0, N);
}

// round 13
// speedup vs baseline: 1.0264x; 1.0264x over previous
#include <cuda_runtime.h>
#include <cuda_fp16.h>
#include <cstdint>

#define NN 100000
#define NE 1600000
#define D  128
#define NPAD (NN + 128)

typedef unsigned int u32;
typedef unsigned long long u64;

// ---- scratch (static device globals; allocation-free) ----
__device__ int    g_rowptr[NN + 1];
__device__ int    g_cursor[NN];
__device__ int    g_col[NE];
__device__ u64    g_bstate[128];
__device__ __align__(16) __half g_hh [(size_t)NPAD * D];  // h (fp16)
__device__ __align__(16) __half g_yl [(size_t)NPAD * D];  // layer-1 A@W_l
__device__ __align__(16) __half g_z  [(size_t)NPAD * D];  // layer-1 A@W_r + b
__device__ __align__(16) __half g_yl2[(size_t)NPAD * D];  // layer-2 A@W_l
__device__ __align__(16) __half g_z2 [(size_t)NPAD * D];  // layer-2 A@W_r + b
__device__ __align__(16) u32 g_B[4][64 * 128];            // fp16 weights k-pair packed

// ---------------- helpers ----------------
__device__ __forceinline__ u32 pack2(__half a, __half b) {
    __half2 h = __halves2half2(a, b);
    return *(u32*)&h;
}
__device__ __forceinline__ void mma16816(float* c, const u32* a, const u32* b) {
    asm volatile(
        "mma.sync.aligned.m16n8k16.row.col.f32.f16.f16.f32 "
        "{%0,%1,%2,%3}, {%4,%5,%6,%7}, {%8,%9}, {%0,%1,%2,%3};"
        : "+f"(c[0]), "+f"(c[1]), "+f"(c[2]), "+f"(c[3])
        : "r"(a[0]), "r"(a[1]), "r"(a[2]), "r"(a[3]), "r"(b[0]), "r"(b[1]));
}

// ---------------- CSR build ----------------
__global__ void k_zero(int n) {
    int i = blockIdx.x * blockDim.x + threadIdx.x;
    if (i < 128) g_bstate[i] = 0ULL;
    if (i < n) g_cursor[i] = 0;
}
__global__ void k_hist(const int* __restrict__ dst, int e4) {
    int i = blockIdx.x * blockDim.x + threadIdx.x;
    if (i >= e4) return;
    int4 d = ((const int4*)dst)[i];
    atomicAdd(&g_cursor[d.x], 1);
    atomicAdd(&g_cursor[d.y], 1);
    atomicAdd(&g_cursor[d.z], 1);
    atomicAdd(&g_cursor[d.w], 1);
}
// single-pass decoupled-lookback scan: counts -> rowptr/cursor (exclusive)
__global__ void k_scanLB(int n, int e) {
    __shared__ int sh[1024];
    __shared__ int s_T;
    __shared__ int s_prefix;
    int bid = blockIdx.x, t = threadIdx.x;
    int i = bid * 1024 + t;
    int v = (i < n) ? g_cursor[i] : 0;
    sh[t] = v;
    __syncthreads();
    for (int off = 1; off < 1024; off <<= 1) {
        int w = (t >= off) ? sh[t - off] : 0;
        __syncthreads();
        sh[t] += w;
        __syncthreads();
    }
    if (t == 1023) s_T = sh[1023];
    if (t == 0 && bid == 0) s_prefix = 0;
    __syncthreads();
    int T = s_T;

    if (t == 0) {
        u64 st = ((u64)(unsigned)T << 32) | (bid == 0 ? 2ULL : 1ULL);
        atomicExch(&g_bstate[bid], st);
    }
    if (t < 32 && bid > 0) {
        int lane = t;
        int prefix = 0;
        int base = bid - 1;
        while (true) {
            int j = base - lane;
            u64 s = (j >= 0) ? *(volatile u64*)&g_bstate[j] : 2ULL;
            unsigned f = (unsigned)(s & 3ULL);
            if (__all_sync(0xFFFFFFFFu, f != 0u)) {
                int val = (int)(unsigned)(s >> 32);
                unsigned pm = __ballot_sync(0xFFFFFFFFu, f == 2u);
                if (pm) {
                    int fp = __ffs(pm) - 1;
                    int xx = (lane <= fp) ? val : 0;
                    #pragma unroll
                    for (int o = 16; o; o >>= 1) xx += __shfl_xor_sync(0xFFFFFFFFu, xx, o);
                    prefix += xx;
                    break;
                } else {
                    int xx = val;
                    #pragma unroll
                    for (int o = 16; o; o >>= 1) xx += __shfl_xor_sync(0xFFFFFFFFu, xx, o);
                    prefix += xx;
                    base -= 32;
                }
            }
        }
        if (lane == 0) {
            atomicExch(&g_bstate[bid], ((u64)(unsigned)(prefix + T) << 32) | 2ULL);
            s_prefix = prefix;
        }
    }
    __syncthreads();
    int r = s_prefix + sh[t] - v;
    if (i < n) {
        g_rowptr[i] = r;
        g_cursor[i] = r;
    }
    if (bid == 0 && t == 0) g_rowptr[n] = e;
}
__global__ void k_scatter(const int* __restrict__ src, const int* __restrict__ dst, int e4) {
    int i = blockIdx.x * blockDim.x + threadIdx.x;
    if (i >= e4) return;
    int4 s = ((const int4*)src)[i];
    int4 d = ((const int4*)dst)[i];
    int p0 = atomicAdd(&g_cursor[d.x], 1); g_col[p0] = s.x;
    int p1 = atomicAdd(&g_cursor[d.y], 1); g_col[p1] = s.y;
    int p2 = atomicAdd(&g_cursor[d.z], 1); g_col[p2] = s.z;
    int p3 = atomicAdd(&g_cursor[d.w], 1); g_col[p3] = s.w;
}

// ---------------- weight prep: fp32 W[k][n] -> fp16 k-pair-packed [kp][n] ----------------
__global__ void k_prepB(const float* __restrict__ W0, const float* __restrict__ W1,
                        const float* __restrict__ W2, const float* __restrict__ W3) {
    const float* Ws[4] = {W0, W1, W2, W3};
    const float* W = Ws[blockIdx.x];
    u32* b = g_B[blockIdx.x];
    for (int u = threadIdx.x; u < 64 * 128; u += blockDim.x) {
        int kp = u >> 7, n = u & 127;
        b[u] = pack2(__float2half_rn(W[(2 * kp) * D + n]),
                     __float2half_rn(W[(2 * kp + 1) * D + n]));
    }
}

// ---------------- HMMA cat-GEMM: [yl | z] = A @ [Bl | Br] (+bias on z) ----------------
#define AS 68
#define BS 264
#define SM_U32_TOTAL (128 * AS + 64 * BS)

__global__ __launch_bounds__(256, 1) void k_gemm(
    const float* __restrict__ A32, const __half* __restrict__ A16, int a32,
    const u32* __restrict__ Bg0, const u32* __restrict__ Bg1,
    const float* __restrict__ bias,
    __half* __restrict__ yl, __half* __restrict__ z, int M, int blk0)
{
    extern __shared__ __align__(16) u32 sm[];
    u32* Asm = sm;
    u32* Bsm = sm + 128 * AS;

    int tid = threadIdx.x, wid = tid >> 5, lane = tid & 31;
    int g = lane >> 2, tg = lane & 3;
    int wm = (wid & 1) * 64, wn = (wid >> 1) * 64;
    int m0 = (blk0 + blockIdx.x) * 128;

    for (int u = tid; u < 2048; u += 256) {
        int r = u >> 5, c4 = u & 31;
        *(uint4*)&Bsm[r * BS + c4 * 4]       = ((const uint4*)Bg0)[u];
        *(uint4*)&Bsm[r * BS + 128 + c4 * 4] = ((const uint4*)Bg1)[u];
    }
    if (a32) {
        for (int u = tid; u < 2048; u += 256) {
            int r = u >> 4, c4 = u & 15;
            int gr = m0 + r;
            float4 fa = make_float4(0.f, 0.f, 0.f, 0.f), fb = fa;
            if (gr < M) {
                const float4* p = (const float4*)(A32 + (size_t)gr * D + c4 * 8);
                fa = p[0]; fb = p[1];
            }
            *(uint4*)&Asm[r * AS + c4 * 4] = make_uint4(
                pack2(__float2half_rn(fa.x), __float2half_rn(fa.y)),
                pack2(__float2half_rn(fa.z), __float2half_rn(fa.w)),
                pack2(__float2half_rn(fb.x), __float2half_rn(fb.y)),
                pack2(__float2half_rn(fb.z), __float2half_rn(fb.w)));
        }
    } else {
        const u32* Ag = (const u32*)A16;
        for (int u = tid; u < 2048; u += 256) {
            int r = u >> 4, c4 = u & 15;
            *(uint4*)&Asm[r * AS + c4 * 4] =
                *(const uint4*)(Ag + (size_t)(m0 + r) * 64 + c4 * 4);
        }
    }
    __syncthreads();

    float acc[4][8][4];
    #pragma unroll
    for (int mt = 0; mt < 4; ++mt)
        #pragma unroll
        for (int nt = 0; nt < 8; ++nt)
            #pragma unroll
            for (int c = 0; c < 4; ++c) acc[mt][nt][c] = 0.f;

    #pragma unroll
    for (int ks = 0; ks < 8; ++ks) {
        u32 afr[4][4];
        #pragma unroll
        for (int mt = 0; mt < 4; ++mt) {
            int r = wm + mt * 16 + g;
            afr[mt][0] = Asm[r * AS + ks * 8 + tg];
            afr[mt][1] = Asm[(r + 8) * AS + ks * 8 + tg];
            afr[mt][2] = Asm[r * AS + ks * 8 + tg + 4];
            afr[mt][3] = Asm[(r + 8) * AS + ks * 8 + tg + 4];
        }
        u32 bfr[8][2];
        #pragma unroll
        for (int nt = 0; nt < 8; ++nt) {
            int n = wn + nt * 8 + g;
            bfr[nt][0] = Bsm[(ks * 8 + tg) * BS + n];
            bfr[nt][1] = Bsm[(ks * 8 + tg + 4) * BS + n];
        }
        #pragma unroll
        for (int mt = 0; mt < 4; ++mt)
            #pragma unroll
            for (int nt = 0; nt < 8; ++nt)
                mma16816(acc[mt][nt], afr[mt], bfr[nt]);
    }

    #pragma unroll
    for (int nt = 0; nt < 8; ++nt) {
        int ccol = wn + nt * 8 + tg * 2;
        if (ccol < 128) {
            #pragma unroll
            for (int mt = 0; mt < 4; ++mt) {
                int r0 = m0 + wm + mt * 16 + g;
                *(__half2*)(yl + (size_t)r0 * D + ccol) =
                    __floats2half2_rn(acc[mt][nt][0], acc[mt][nt][1]);
                *(__half2*)(yl + (size_t)(r0 + 8) * D + ccol) =
                    __floats2half2_rn(acc[mt][nt][2], acc[mt][nt][3]);
            }
        } else {
            int zc = ccol - 128;
            float bv0 = __ldg(bias + zc), bv1 = __ldg(bias + zc + 1);
            #pragma unroll
            for (int mt = 0; mt < 4; ++mt) {
                int r0 = m0 + wm + mt * 16 + g;
                *(__half2*)(z + (size_t)r0 * D + zc) =
                    __floats2half2_rn(acc[mt][nt][0] + bv0, acc[mt][nt][1] + bv1);
                *(__half2*)(z + (size_t)(r0 + 8) * D + zc) =
                    __floats2half2_rn(acc[mt][nt][2] + bv0, acc[mt][nt][3] + bv1);
            }
        }
    }
}

// ---------------- fused mean-agg + add-self + (relu), node range [w0, wend) ----------------
__global__ void k_aggf(const __half* __restrict__ yl, const __half* __restrict__ z,
                       __half* __restrict__ outh, float* __restrict__ outf,
                       int relu, int w0, int wend)
{
    int w    = w0 + ((blockIdx.x * blockDim.x + threadIdx.x) >> 5);
    int lane = threadIdx.x & 31;
    if (w >= wend) return;
    int beg = g_rowptr[w], end = g_rowptr[w + 1];
    float a0 = 0.f, a1 = 0.f, a2 = 0.f, a3 = 0.f;
    int j = beg;
    for (; j + 8 <= end; j += 8) {
        uint2 u[8];
        #pragma unroll
        for (int q = 0; q < 8; ++q) {
            int s = g_col[j + q];
            u[q] = __ldcs((const uint2*)(yl + (size_t)s * D) + lane);
        }
        #pragma unroll
        for (int q = 0; q < 8; ++q) {
            float2 f0 = __half22float2(*(__half2*)&u[q].x);
            float2 f1 = __half22float2(*(__half2*)&u[q].y);
            a0 += f0.x; a1 += f0.y; a2 += f1.x; a3 += f1.y;
        }
    }
    for (; j < end; ++j) {
        int s = g_col[j];
        uint2 u = __ldcs((const uint2*)(yl + (size_t)s * D) + lane);
        float2 f0 = __half22float2(*(__half2*)&u.x);
        float2 f1 = __half22float2(*(__half2*)&u.y);
        a0 += f0.x; a1 += f0.y; a2 += f1.x; a3 += f1.y;
    }
    int deg = end - beg;
    float inv = 1.0f / (float)(deg > 1 ? deg : 1);
    uint2 zu = *((const uint2*)(z + (size_t)w * D) + lane);
    float2 z0 = __half22float2(*(__half2*)&zu.x);
    float2 z1 = __half22float2(*(__half2*)&zu.y);
    float v0 = a0 * inv + z0.x, v1 = a1 * inv + z0.y;
    float v2 = a2 * inv + z1.x, v3 = a3 * inv + z1.y;
    if (relu) {
        v0 = v0 > 0.f ? v0 : 0.f; v1 = v1 > 0.f ? v1 : 0.f;
        v2 = v2 > 0.f ? v2 : 0.f; v3 = v3 > 0.f ? v3 : 0.f;
    }
    if (outh) {
        *((uint2*)(outh + (size_t)w * D) + lane) =
            make_uint2(pack2(__float2half_rn(v0), __float2half_rn(v1)),
                       pack2(__float2half_rn(v2), __float2half_rn(v3)));
    } else {
        *((float4*)(outf + (size_t)w * D) + lane) = make_float4(v0, v1, v2, v3);
    }
}

// ---------------- launch ----------------
extern "C" void kernel_launch(void* const* d_in, const int* in_sizes, int n_in,
                              void* d_out, int out_size)
{
    const float* x   = (const float*)d_in[0];
    const int*   ei  = (const int*)d_in[1];
    const float* W1l = (const float*)d_in[2];
    const float* b1  = (const float*)d_in[3];
    const float* W1r = (const float*)d_in[4];
    const float* W2l = (const float*)d_in[5];
    const float* b2  = (const float*)d_in[6];
    const float* W2r = (const float*)d_in[7];
    float* out = (float*)d_out;

    int N = in_sizes[0] / D;
    int E = in_sizes[1] / 2;
    const int* src = ei;
    const int* dst = ei + E;

    __half *hh, *yl, *z, *yl2, *z2;
    u32 *B0, *B1, *B2, *B3;
    cudaGetSymbolAddress((void**)&hh,  g_hh);
    cudaGetSymbolAddress((void**)&yl,  g_yl);
    cudaGetSymbolAddress((void**)&z,   g_z);
    cudaGetSymbolAddress((void**)&yl2, g_yl2);
    cudaGetSymbolAddress((void**)&z2,  g_z2);
    {
        u32* bb;
        cudaGetSymbolAddress((void**)&bb, g_B);
        B0 = bb; B1 = bb + 8192; B2 = bb + 16384; B3 = bb + 24576;
    }

    cudaFuncSetAttribute(k_gemm, cudaFuncAttributeMaxDynamicSharedMemorySize,
                         SM_U32_TOTAL * 4);

    static cudaStream_t sB = nullptr;
    static cudaEvent_t evFork = nullptr, evJoin = nullptr, evLo = nullptr, evHi = nullptr;
    if (!sB) {
        cudaStreamCreateWithFlags(&sB, cudaStreamNonBlocking);
        cudaEventCreateWithFlags(&evFork, cudaEventDisableTiming);
        cudaEventCreateWithFlags(&evJoin, cudaEventDisableTiming);
        cudaEventCreateWithFlags(&evLo, cudaEventDisableTiming);
        cudaEventCreateWithFlags(&evHi, cudaEventDisableTiming);
    }

    int e4 = (E + 3) / 4;
    int nb = (N + 1023) / 1024;
    int tiles   = (N + 127) / 128;
    int tilesLo = tiles / 2;
    int split   = tilesLo * 128;             // node/row split on tile boundary

    // fork: CSR build on side stream
    cudaEventRecord(evFork, 0);
    cudaStreamWaitEvent(sB, evFork, 0);
    k_zero   <<<(N + 255) / 256, 256, 0, sB>>>(N);
    k_hist   <<<(e4 + 255) / 256, 256, 0, sB>>>(dst, e4);
    k_scanLB <<<nb, 1024, 0, sB>>>(N, E);
    k_scatter<<<(e4 + 255) / 256, 256, 0, sB>>>(src, dst, e4);
    cudaEventRecord(evJoin, sB);

    // main stream: weights + layer-1 GEMM (reads fp32 x directly) -> yl/z
    k_prepB<<<4, 256>>>(W1l, W1r, W2l, W2r);
    k_gemm <<<tiles, 256, SM_U32_TOTAL * 4>>>(
        x, nullptr, 1, B0, B1, b1, yl, z, N, 0);

    // join CSR, then staggered layer-1 agg + pipelined layer-2 GEMM (to yl2/z2)
    cudaStreamWaitEvent(0, evJoin, 0);
    // aggf1 lower half (nodes [0, split)) : yl/z -> hh
    k_aggf<<<(split * 32 + 255) / 256, 256>>>(yl, z, hh, nullptr, 1, 0, split);
    cudaEventRecord(evLo, 0);
    // aggf1 upper half on side stream (reads yl/z), overlapped with gemm2_lo
    cudaStreamWaitEvent(sB, evLo, 0);
    k_aggf<<<((N - split) * 32 + 255) / 256, 256, 0, sB>>>(yl, z, hh, nullptr, 1, split, N);
    cudaEventRecord(evHi, sB);
    // gemm2 lower half: reads hh[0,split), writes yl2/z2 (no alias with yl/z)
    k_gemm<<<tilesLo, 256, SM_U32_TOTAL * 4>>>(
        nullptr, hh, 0, B2, B3, b2, yl2, z2, N, 0);
    // gemm2 upper half after aggf1_hi
    cudaStreamWaitEvent(0, evHi, 0);
    k_gemm<<<tiles - tilesLo, 256, SM_U32_TOTAL * 4>>>(
        nullptr, hh, 0, B2, B3, b2, yl2, z2, N, tilesLo);
    // layer-2 agg over all nodes from yl2/z2
    k_aggf<<<(N * 32 + 255) / 256, 256>>>(yl2, z2, nullptr, out, 0, 0, N);
}

// round 14
// speedup vs baseline: 1.1338x; 1.1047x over previous
#include <cuda_runtime.h>
#include <cuda_fp16.h>
#include <cstdint>

#define NN 100000
#define NE 1600000
#define D  128
#define NPAD (NN + 128)

typedef unsigned int u32;
typedef unsigned long long u64;

// ---- scratch (static device globals; allocation-free) ----
__device__ int    g_rowptr[NN + 1];
__device__ int    g_cursor[NN];
__device__ int    g_col[NE];
__device__ int    g_rank[NE];
__device__ u64    g_bstate[128];
__device__ __align__(16) __half g_hh[(size_t)NPAD * D];   // h (fp16)
__device__ __align__(16) __half g_yl[(size_t)NPAD * D];   // A@W_l (fp16)
__device__ __align__(16) __half g_z [(size_t)NPAD * D];   // A@W_r + b (fp16)
__device__ __align__(16) u32 g_B[4][64 * 128];            // fp16 weights k-pair packed

// ---------------- helpers ----------------
__device__ __forceinline__ u32 pack2(__half a, __half b) {
    __half2 h = __halves2half2(a, b);
    return *(u32*)&h;
}
__device__ __forceinline__ void mma16816(float* c, const u32* a, const u32* b) {
    asm volatile(
        "mma.sync.aligned.m16n8k16.row.col.f32.f16.f16.f32 "
        "{%0,%1,%2,%3}, {%4,%5,%6,%7}, {%8,%9}, {%0,%1,%2,%3};"
        : "+f"(c[0]), "+f"(c[1]), "+f"(c[2]), "+f"(c[3])
        : "r"(a[0]), "r"(a[1]), "r"(a[2]), "r"(a[3]), "r"(b[0]), "r"(b[1]));
}

// ---------------- CSR build ----------------
__global__ void k_zero(int n) {
    int i = blockIdx.x * blockDim.x + threadIdx.x;
    if (i < 128) g_bstate[i] = 0ULL;
    if (i < n) g_cursor[i] = 0;
}
// count + record per-edge rank within its destination bucket
__global__ void k_hist(const int* __restrict__ dst, int e4) {
    int i = blockIdx.x * blockDim.x + threadIdx.x;
    if (i >= e4) return;
    int4 d = ((const int4*)dst)[i];
    int r0 = atomicAdd(&g_cursor[d.x], 1);
    int r1 = atomicAdd(&g_cursor[d.y], 1);
    int r2 = atomicAdd(&g_cursor[d.z], 1);
    int r3 = atomicAdd(&g_cursor[d.w], 1);
    ((int4*)g_rank)[i] = make_int4(r0, r1, r2, r3);
}
// single-pass decoupled-lookback scan: counts -> rowptr (exclusive)
__global__ void k_scanLB(int n, int e) {
    __shared__ int sh[1024];
    __shared__ int s_T;
    __shared__ int s_prefix;
    int bid = blockIdx.x, t = threadIdx.x;
    int i = bid * 1024 + t;
    int v = (i < n) ? g_cursor[i] : 0;
    sh[t] = v;
    __syncthreads();
    for (int off = 1; off < 1024; off <<= 1) {
        int w = (t >= off) ? sh[t - off] : 0;
        __syncthreads();
        sh[t] += w;
        __syncthreads();
    }
    if (t == 1023) s_T = sh[1023];
    if (t == 0 && bid == 0) s_prefix = 0;
    __syncthreads();
    int T = s_T;

    if (t == 0) {
        u64 st = ((u64)(unsigned)T << 32) | (bid == 0 ? 2ULL : 1ULL);
        atomicExch(&g_bstate[bid], st);
    }
    if (t < 32 && bid > 0) {
        int lane = t;
        int prefix = 0;
        int base = bid - 1;
        while (true) {
            int j = base - lane;
            u64 s = (j >= 0) ? *(volatile u64*)&g_bstate[j] : 2ULL;
            unsigned f = (unsigned)(s & 3ULL);
            if (__all_sync(0xFFFFFFFFu, f != 0u)) {
                int val = (int)(unsigned)(s >> 32);
                unsigned pm = __ballot_sync(0xFFFFFFFFu, f == 2u);
                if (pm) {
                    int fp = __ffs(pm) - 1;
                    int xx = (lane <= fp) ? val : 0;
                    #pragma unroll
                    for (int o = 16; o; o >>= 1) xx += __shfl_xor_sync(0xFFFFFFFFu, xx, o);
                    prefix += xx;
                    break;
                } else {
                    int xx = val;
                    #pragma unroll
                    for (int o = 16; o; o >>= 1) xx += __shfl_xor_sync(0xFFFFFFFFu, xx, o);
                    prefix += xx;
                    base -= 32;
                }
            }
        }
        if (lane == 0) {
            atomicExch(&g_bstate[bid], ((u64)(unsigned)(prefix + T) << 32) | 2ULL);
            s_prefix = prefix;
        }
    }
    __syncthreads();
    int r = s_prefix + sh[t] - v;
    if (i < n) g_rowptr[i] = r;
    if (bid == 0 && t == 0) g_rowptr[n] = e;
}
// atomic-free scatter: position = rowptr[dst] + rank
__global__ void k_scatter(const int* __restrict__ src, const int* __restrict__ dst, int e4) {
    int i = blockIdx.x * blockDim.x + threadIdx.x;
    if (i >= e4) return;
    int4 s = ((const int4*)src)[i];
    int4 d = ((const int4*)dst)[i];
    int4 r = ((const int4*)g_rank)[i];
    int p0 = g_rowptr[d.x] + r.x;
    int p1 = g_rowptr[d.y] + r.y;
    int p2 = g_rowptr[d.z] + r.z;
    int p3 = g_rowptr[d.w] + r.w;
    g_col[p0] = s.x;
    g_col[p1] = s.y;
    g_col[p2] = s.z;
    g_col[p3] = s.w;
}

// ---------------- weight prep: fp32 W[k][n] -> fp16 k-pair-packed [kp][n] ----------------
__global__ void k_prepB(const float* __restrict__ W0, const float* __restrict__ W1,
                        const float* __restrict__ W2, const float* __restrict__ W3) {
    const float* Ws[4] = {W0, W1, W2, W3};
    const float* W = Ws[blockIdx.x];
    u32* b = g_B[blockIdx.x];
    for (int u = threadIdx.x; u < 64 * 128; u += blockDim.x) {
        int kp = u >> 7, n = u & 127;
        b[u] = pack2(__float2half_rn(W[(2 * kp) * D + n]),
                     __float2half_rn(W[(2 * kp + 1) * D + n]));
    }
}

// ---------------- HMMA cat-GEMM: [yl | z] = A @ [Bl | Br] (+bias on z) ----------------
#define AS 68
#define BS 264
#define SM_U32_TOTAL (128 * AS + 64 * BS)

__global__ __launch_bounds__(256, 1) void k_gemm(
    const float* __restrict__ A32, const __half* __restrict__ A16, int a32,
    const u32* __restrict__ Bg0, const u32* __restrict__ Bg1,
    const float* __restrict__ bias,
    __half* __restrict__ yl, __half* __restrict__ z, int M)
{
    extern __shared__ __align__(16) u32 sm[];
    u32* Asm = sm;
    u32* Bsm = sm + 128 * AS;

    int tid = threadIdx.x, wid = tid >> 5, lane = tid & 31;
    int g = lane >> 2, tg = lane & 3;
    int wm = (wid & 1) * 64, wn = (wid >> 1) * 64;
    int m0 = blockIdx.x * 128;

    for (int u = tid; u < 2048; u += 256) {
        int r = u >> 5, c4 = u & 31;
        *(uint4*)&Bsm[r * BS + c4 * 4]       = ((const uint4*)Bg0)[u];
        *(uint4*)&Bsm[r * BS + 128 + c4 * 4] = ((const uint4*)Bg1)[u];
    }
    if (a32) {
        for (int u = tid; u < 2048; u += 256) {
            int r = u >> 4, c4 = u & 15;
            int gr = m0 + r;
            float4 fa = make_float4(0.f, 0.f, 0.f, 0.f), fb = fa;
            if (gr < M) {
                const float4* p = (const float4*)(A32 + (size_t)gr * D + c4 * 8);
                fa = p[0]; fb = p[1];
            }
            *(uint4*)&Asm[r * AS + c4 * 4] = make_uint4(
                pack2(__float2half_rn(fa.x), __float2half_rn(fa.y)),
                pack2(__float2half_rn(fa.z), __float2half_rn(fa.w)),
                pack2(__float2half_rn(fb.x), __float2half_rn(fb.y)),
                pack2(__float2half_rn(fb.z), __float2half_rn(fb.w)));
        }
    } else {
        const u32* Ag = (const u32*)A16;
        for (int u = tid; u < 2048; u += 256) {
            int r = u >> 4, c4 = u & 15;
            *(uint4*)&Asm[r * AS + c4 * 4] =
                *(const uint4*)(Ag + (size_t)(m0 + r) * 64 + c4 * 4);
        }
    }
    __syncthreads();

    float acc[4][8][4];
    #pragma unroll
    for (int mt = 0; mt < 4; ++mt)
        #pragma unroll
        for (int nt = 0; nt < 8; ++nt)
            #pragma unroll
            for (int c = 0; c < 4; ++c) acc[mt][nt][c] = 0.f;

    #pragma unroll
    for (int ks = 0; ks < 8; ++ks) {
        u32 afr[4][4];
        #pragma unroll
        for (int mt = 0; mt < 4; ++mt) {
            int r = wm + mt * 16 + g;
            afr[mt][0] = Asm[r * AS + ks * 8 + tg];
            afr[mt][1] = Asm[(r + 8) * AS + ks * 8 + tg];
            afr[mt][2] = Asm[r * AS + ks * 8 + tg + 4];
            afr[mt][3] = Asm[(r + 8) * AS + ks * 8 + tg + 4];
        }
        u32 bfr[8][2];
        #pragma unroll
        for (int nt = 0; nt < 8; ++nt) {
            int n = wn + nt * 8 + g;
            bfr[nt][0] = Bsm[(ks * 8 + tg) * BS + n];
            bfr[nt][1] = Bsm[(ks * 8 + tg + 4) * BS + n];
        }
        #pragma unroll
        for (int mt = 0; mt < 4; ++mt)
            #pragma unroll
            for (int nt = 0; nt < 8; ++nt)
                mma16816(acc[mt][nt], afr[mt], bfr[nt]);
    }

    #pragma unroll
    for (int nt = 0; nt < 8; ++nt) {
        int ccol = wn + nt * 8 + tg * 2;
        if (ccol < 128) {
            #pragma unroll
            for (int mt = 0; mt < 4; ++mt) {
                int r0 = m0 + wm + mt * 16 + g;
                *(__half2*)(yl + (size_t)r0 * D + ccol) =
                    __floats2half2_rn(acc[mt][nt][0], acc[mt][nt][1]);
                *(__half2*)(yl + (size_t)(r0 + 8) * D + ccol) =
                    __floats2half2_rn(acc[mt][nt][2], acc[mt][nt][3]);
            }
        } else {
            int zc = ccol - 128;
            float bv0 = __ldg(bias + zc), bv1 = __ldg(bias + zc + 1);
            #pragma unroll
            for (int mt = 0; mt < 4; ++mt) {
                int r0 = m0 + wm + mt * 16 + g;
                *(__half2*)(z + (size_t)r0 * D + zc) =
                    __floats2half2_rn(acc[mt][nt][0] + bv0, acc[mt][nt][1] + bv1);
                *(__half2*)(z + (size_t)(r0 + 8) * D + zc) =
                    __floats2half2_rn(acc[mt][nt][2] + bv0, acc[mt][nt][3] + bv1);
            }
        }
    }
}

// ---------------- fused mean-agg + add-self + (relu) ----------------
__global__ void k_aggf(const __half* __restrict__ yl, const __half* __restrict__ z,
                       __half* __restrict__ outh, float* __restrict__ outf,
                       int relu, int n)
{
    int w    = (blockIdx.x * blockDim.x + threadIdx.x) >> 5;
    int lane = threadIdx.x & 31;
    if (w >= n) return;
    int beg = g_rowptr[w], end = g_rowptr[w + 1];
    float a0 = 0.f, a1 = 0.f, a2 = 0.f, a3 = 0.f;
    int j = beg;
    for (; j + 8 <= end; j += 8) {
        uint2 u[8];
        #pragma unroll
        for (int q = 0; q < 8; ++q) {
            int s = g_col[j + q];
            u[q] = *((const uint2*)(yl + (size_t)s * D) + lane);
        }
        #pragma unroll
        for (int q = 0; q < 8; ++q) {
            float2 f0 = __half22float2(*(__half2*)&u[q].x);
            float2 f1 = __half22float2(*(__half2*)&u[q].y);
            a0 += f0.x; a1 += f0.y; a2 += f1.x; a3 += f1.y;
        }
    }
    for (; j < end; ++j) {
        int s = g_col[j];
        uint2 u = *((const uint2*)(yl + (size_t)s * D) + lane);
        float2 f0 = __half22float2(*(__half2*)&u.x);
        float2 f1 = __half22float2(*(__half2*)&u.y);
        a0 += f0.x; a1 += f0.y; a2 += f1.x; a3 += f1.y;
    }
    int deg = end - beg;
    float inv = 1.0f / (float)(deg > 1 ? deg : 1);
    uint2 zu = *((const uint2*)(z + (size_t)w * D) + lane);
    float2 z0 = __half22float2(*(__half2*)&zu.x);
    float2 z1 = __half22float2(*(__half2*)&zu.y);
    float v0 = a0 * inv + z0.x, v1 = a1 * inv + z0.y;
    float v2 = a2 * inv + z1.x, v3 = a3 * inv + z1.y;
    if (relu) {
        v0 = v0 > 0.f ? v0 : 0.f; v1 = v1 > 0.f ? v1 : 0.f;
        v2 = v2 > 0.f ? v2 : 0.f; v3 = v3 > 0.f ? v3 : 0.f;
    }
    if (outh) {
        *((uint2*)(outh + (size_t)w * D) + lane) =
            make_uint2(pack2(__float2half_rn(v0), __float2half_rn(v1)),
                       pack2(__float2half_rn(v2), __float2half_rn(v3)));
    } else {
        *((float4*)(outf + (size_t)w * D) + lane) = make_float4(v0, v1, v2, v3);
    }
}

// ---------------- launch ----------------
extern "C" void kernel_launch(void* const* d_in, const int* in_sizes, int n_in,
                              void* d_out, int out_size)
{
    const float* x   = (const float*)d_in[0];
    const int*   ei  = (const int*)d_in[1];
    const float* W1l = (const float*)d_in[2];
    const float* b1  = (const float*)d_in[3];
    const float* W1r = (const float*)d_in[4];
    const float* W2l = (const float*)d_in[5];
    const float* b2  = (const float*)d_in[6];
    const float* W2r = (const float*)d_in[7];
    float* out = (float*)d_out;

    int N = in_sizes[0] / D;
    int E = in_sizes[1] / 2;
    const int* src = ei;
    const int* dst = ei + E;

    __half *hh, *yl, *z;
    u32 *B0, *B1, *B2, *B3;
    cudaGetSymbolAddress((void**)&hh, g_hh);
    cudaGetSymbolAddress((void**)&yl, g_yl);
    cudaGetSymbolAddress((void**)&z,  g_z);
    {
        u32* bb;
        cudaGetSymbolAddress((void**)&bb, g_B);
        B0 = bb; B1 = bb + 8192; B2 = bb + 16384; B3 = bb + 24576;
    }

    cudaFuncSetAttribute(k_gemm, cudaFuncAttributeMaxDynamicSharedMemorySize,
                         SM_U32_TOTAL * 4);

    static cudaStream_t sB = nullptr;
    static cudaEvent_t evFork = nullptr, evJoin = nullptr;
    if (!sB) {
        cudaStreamCreateWithFlags(&sB, cudaStreamNonBlocking);
        cudaEventCreateWithFlags(&evFork, cudaEventDisableTiming);
        cudaEventCreateWithFlags(&evJoin, cudaEventDisableTiming);
    }

    int e4 = (E + 3) / 4;
    int nb = (N + 1023) / 1024;
    int aggBlocks  = (N * 32 + 255) / 256;
    int gemmBlocks = (N + 127) / 128;

    // fork: CSR build on side stream (rank-based, single atomic pass)
    cudaEventRecord(evFork, 0);
    cudaStreamWaitEvent(sB, evFork, 0);
    k_zero   <<<(N + 255) / 256, 256, 0, sB>>>(N);
    k_hist   <<<(e4 + 255) / 256, 256, 0, sB>>>(dst, e4);
    k_scanLB <<<nb, 1024, 0, sB>>>(N, E);
    k_scatter<<<(e4 + 255) / 256, 256, 0, sB>>>(src, dst, e4);
    cudaEventRecord(evJoin, sB);

    // main stream: weights + layer-1 GEMM (reads fp32 x directly)
    k_prepB<<<4, 256>>>(W1l, W1r, W2l, W2r);
    k_gemm <<<gemmBlocks, 256, SM_U32_TOTAL * 4>>>(
        x, nullptr, 1, B0, B1, b1, yl, z, N);

    // join, then agg/gemm/agg
    cudaStreamWaitEvent(0, evJoin, 0);
    k_aggf<<<aggBlocks, 256>>>(yl, z, hh, nullptr, 1, N);
    k_gemm<<<gemmBlocks, 256, SM_U32_TOTAL * 4>>>(
        nullptr, hh, 0, B2, B3, b2, yl, z, N);
    k_aggf<<<aggBlocks, 256>>>(yl, z, nullptr, out, 0, N);
}

// round 15
// speedup vs baseline: 1.1396x; 1.0052x over previous
#include <cuda_runtime.h>
#include <cuda_fp16.h>
#include <cstdint>

#define NN 100000
#define NE 1600000
#define D  128
#define NPAD (NN + 128)

typedef unsigned int u32;
typedef unsigned long long u64;

// ---- scratch (static device globals; allocation-free) ----
// g_cursor/g_bstate are zero at module load; kernels restore them to zero
// each run so graph replays are deterministic without a dedicated zero pass.
__device__ int    g_rowptr[NN + 1];
__device__ int    g_cursor[NN];
__device__ int    g_col[NE];
__device__ int    g_rank[NE];
__device__ u64    g_bstate[128];
__device__ __align__(16) __half g_hh[(size_t)NPAD * D];   // h (fp16)
__device__ __align__(16) __half g_yl[(size_t)NPAD * D];   // A@W_l (fp16)
__device__ __align__(16) __half g_z [(size_t)NPAD * D];   // A@W_r + b (fp16)
__device__ __align__(16) u32 g_B[4][64 * 128];            // fp16 weights k-pair packed

// ---------------- helpers ----------------
__device__ __forceinline__ u32 pack2(__half a, __half b) {
    __half2 h = __halves2half2(a, b);
    return *(u32*)&h;
}
__device__ __forceinline__ void mma16816(float* c, const u32* a, const u32* b) {
    asm volatile(
        "mma.sync.aligned.m16n8k16.row.col.f32.f16.f16.f32 "
        "{%0,%1,%2,%3}, {%4,%5,%6,%7}, {%8,%9}, {%0,%1,%2,%3};"
        : "+f"(c[0]), "+f"(c[1]), "+f"(c[2]), "+f"(c[3])
        : "r"(a[0]), "r"(a[1]), "r"(a[2]), "r"(a[3]), "r"(b[0]), "r"(b[1]));
}

// ---------------- CSR build ----------------
// count + record per-edge rank within its destination bucket.
// Also zeroes g_bstate for the scan (runs before k_scanLB in stream order).
__global__ void k_hist(const int* __restrict__ dst, int e4) {
    int i = blockIdx.x * blockDim.x + threadIdx.x;
    if (i < 128) g_bstate[i] = 0ULL;
    if (i >= e4) return;
    int4 d = ((const int4*)dst)[i];
    int r0 = atomicAdd(&g_cursor[d.x], 1);
    int r1 = atomicAdd(&g_cursor[d.y], 1);
    int r2 = atomicAdd(&g_cursor[d.z], 1);
    int r3 = atomicAdd(&g_cursor[d.w], 1);
    ((int4*)g_rank)[i] = make_int4(r0, r1, r2, r3);
}
// single-pass decoupled-lookback scan: counts -> rowptr (exclusive).
// Restores cursor[i]=0 after consuming it (same thread, after the read).
__global__ void k_scanLB(int n, int e) {
    __shared__ int sh[1024];
    __shared__ int s_T;
    __shared__ int s_prefix;
    int bid = blockIdx.x, t = threadIdx.x;
    int i = bid * 1024 + t;
    int v = (i < n) ? g_cursor[i] : 0;
    sh[t] = v;
    __syncthreads();
    for (int off = 1; off < 1024; off <<= 1) {
        int w = (t >= off) ? sh[t - off] : 0;
        __syncthreads();
        sh[t] += w;
        __syncthreads();
    }
    if (t == 1023) s_T = sh[1023];
    if (t == 0 && bid == 0) s_prefix = 0;
    __syncthreads();
    int T = s_T;

    if (t == 0) {
        u64 st = ((u64)(unsigned)T << 32) | (bid == 0 ? 2ULL : 1ULL);
        atomicExch(&g_bstate[bid], st);
    }
    if (t < 32 && bid > 0) {
        int lane = t;
        int prefix = 0;
        int base = bid - 1;
        while (true) {
            int j = base - lane;
            u64 s = (j >= 0) ? *(volatile u64*)&g_bstate[j] : 2ULL;
            unsigned f = (unsigned)(s & 3ULL);
            if (__all_sync(0xFFFFFFFFu, f != 0u)) {
                int val = (int)(unsigned)(s >> 32);
                unsigned pm = __ballot_sync(0xFFFFFFFFu, f == 2u);
                if (pm) {
                    int fp = __ffs(pm) - 1;
                    int xx = (lane <= fp) ? val : 0;
                    #pragma unroll
                    for (int o = 16; o; o >>= 1) xx += __shfl_xor_sync(0xFFFFFFFFu, xx, o);
                    prefix += xx;
                    break;
                } else {
                    int xx = val;
                    #pragma unroll
                    for (int o = 16; o; o >>= 1) xx += __shfl_xor_sync(0xFFFFFFFFu, xx, o);
                    prefix += xx;
                    base -= 32;
                }
            }
        }
        if (lane == 0) {
            atomicExch(&g_bstate[bid], ((u64)(unsigned)(prefix + T) << 32) | 2ULL);
            s_prefix = prefix;
        }
    }
    __syncthreads();
    int r = s_prefix + sh[t] - v;
    if (i < n) {
        g_rowptr[i] = r;
        g_cursor[i] = 0;          // restore for next graph replay
    }
    if (bid == 0 && t == 0) g_rowptr[n] = e;
}
// atomic-free scatter: position = rowptr[dst] + rank
__global__ void k_scatter(const int* __restrict__ src, const int* __restrict__ dst, int e4) {
    int i = blockIdx.x * blockDim.x + threadIdx.x;
    if (i >= e4) return;
    int4 s = ((const int4*)src)[i];
    int4 d = ((const int4*)dst)[i];
    int4 r = ((const int4*)g_rank)[i];
    int p0 = g_rowptr[d.x] + r.x;
    int p1 = g_rowptr[d.y] + r.y;
    int p2 = g_rowptr[d.z] + r.z;
    int p3 = g_rowptr[d.w] + r.w;
    g_col[p0] = s.x;
    g_col[p1] = s.y;
    g_col[p2] = s.z;
    g_col[p3] = s.w;
}

// ---------------- weight prep: fp32 W[k][n] -> fp16 k-pair-packed [kp][n] ----------------
__global__ void k_prepB(const float* __restrict__ W0, const float* __restrict__ W1,
                        const float* __restrict__ W2, const float* __restrict__ W3) {
    const float* Ws[4] = {W0, W1, W2, W3};
    const float* W = Ws[blockIdx.x];
    u32* b = g_B[blockIdx.x];
    for (int u = threadIdx.x; u < 64 * 128; u += blockDim.x) {
        int kp = u >> 7, n = u & 127;
        b[u] = pack2(__float2half_rn(W[(2 * kp) * D + n]),
                     __float2half_rn(W[(2 * kp + 1) * D + n]));
    }
}

// ---------------- HMMA cat-GEMM: [yl | z] = A @ [Bl | Br] (+bias on z) ----------------
#define AS 68
#define BS 264
#define SM_U32_TOTAL (128 * AS + 64 * BS)

__global__ __launch_bounds__(256, 1) void k_gemm(
    const float* __restrict__ A32, const __half* __restrict__ A16, int a32,
    const u32* __restrict__ Bg0, const u32* __restrict__ Bg1,
    const float* __restrict__ bias,
    __half* __restrict__ yl, __half* __restrict__ z, int M)
{
    extern __shared__ __align__(16) u32 sm[];
    u32* Asm = sm;
    u32* Bsm = sm + 128 * AS;

    int tid = threadIdx.x, wid = tid >> 5, lane = tid & 31;
    int g = lane >> 2, tg = lane & 3;
    int wm = (wid & 1) * 64, wn = (wid >> 1) * 64;
    int m0 = blockIdx.x * 128;

    for (int u = tid; u < 2048; u += 256) {
        int r = u >> 5, c4 = u & 31;
        *(uint4*)&Bsm[r * BS + c4 * 4]       = ((const uint4*)Bg0)[u];
        *(uint4*)&Bsm[r * BS + 128 + c4 * 4] = ((const uint4*)Bg1)[u];
    }
    if (a32) {
        for (int u = tid; u < 2048; u += 256) {
            int r = u >> 4, c4 = u & 15;
            int gr = m0 + r;
            float4 fa = make_float4(0.f, 0.f, 0.f, 0.f), fb = fa;
            if (gr < M) {
                const float4* p = (const float4*)(A32 + (size_t)gr * D + c4 * 8);
                fa = p[0]; fb = p[1];
            }
            *(uint4*)&Asm[r * AS + c4 * 4] = make_uint4(
                pack2(__float2half_rn(fa.x), __float2half_rn(fa.y)),
                pack2(__float2half_rn(fa.z), __float2half_rn(fa.w)),
                pack2(__float2half_rn(fb.x), __float2half_rn(fb.y)),
                pack2(__float2half_rn(fb.z), __float2half_rn(fb.w)));
        }
    } else {
        const u32* Ag = (const u32*)A16;
        for (int u = tid; u < 2048; u += 256) {
            int r = u >> 4, c4 = u & 15;
            *(uint4*)&Asm[r * AS + c4 * 4] =
                *(const uint4*)(Ag + (size_t)(m0 + r) * 64 + c4 * 4);
        }
    }
    __syncthreads();

    float acc[4][8][4];
    #pragma unroll
    for (int mt = 0; mt < 4; ++mt)
        #pragma unroll
        for (int nt = 0; nt < 8; ++nt)
            #pragma unroll
            for (int c = 0; c < 4; ++c) acc[mt][nt][c] = 0.f;

    #pragma unroll
    for (int ks = 0; ks < 8; ++ks) {
        u32 afr[4][4];
        #pragma unroll
        for (int mt = 0; mt < 4; ++mt) {
            int r = wm + mt * 16 + g;
            afr[mt][0] = Asm[r * AS + ks * 8 + tg];
            afr[mt][1] = Asm[(r + 8) * AS + ks * 8 + tg];
            afr[mt][2] = Asm[r * AS + ks * 8 + tg + 4];
            afr[mt][3] = Asm[(r + 8) * AS + ks * 8 + tg + 4];
        }
        u32 bfr[8][2];
        #pragma unroll
        for (int nt = 0; nt < 8; ++nt) {
            int n = wn + nt * 8 + g;
            bfr[nt][0] = Bsm[(ks * 8 + tg) * BS + n];
            bfr[nt][1] = Bsm[(ks * 8 + tg + 4) * BS + n];
        }
        #pragma unroll
        for (int mt = 0; mt < 4; ++mt)
            #pragma unroll
            for (int nt = 0; nt < 8; ++nt)
                mma16816(acc[mt][nt], afr[mt], bfr[nt]);
    }

    #pragma unroll
    for (int nt = 0; nt < 8; ++nt) {
        int ccol = wn + nt * 8 + tg * 2;
        if (ccol < 128) {
            #pragma unroll
            for (int mt = 0; mt < 4; ++mt) {
                int r0 = m0 + wm + mt * 16 + g;
                *(__half2*)(yl + (size_t)r0 * D + ccol) =
                    __floats2half2_rn(acc[mt][nt][0], acc[mt][nt][1]);
                *(__half2*)(yl + (size_t)(r0 + 8) * D + ccol) =
                    __floats2half2_rn(acc[mt][nt][2], acc[mt][nt][3]);
            }
        } else {
            int zc = ccol - 128;
            float bv0 = __ldg(bias + zc), bv1 = __ldg(bias + zc + 1);
            #pragma unroll
            for (int mt = 0; mt < 4; ++mt) {
                int r0 = m0 + wm + mt * 16 + g;
                *(__half2*)(z + (size_t)r0 * D + zc) =
                    __floats2half2_rn(acc[mt][nt][0] + bv0, acc[mt][nt][1] + bv1);
                *(__half2*)(z + (size_t)(r0 + 8) * D + zc) =
                    __floats2half2_rn(acc[mt][nt][2] + bv0, acc[mt][nt][3] + bv1);
            }
        }
    }
}

// ---------------- fused mean-agg + add-self + (relu) ----------------
__global__ void k_aggf(const __half* __restrict__ yl, const __half* __restrict__ z,
                       __half* __restrict__ outh, float* __restrict__ outf,
                       int relu, int n)
{
    int w    = (blockIdx.x * blockDim.x + threadIdx.x) >> 5;
    int lane = threadIdx.x & 31;
    if (w >= n) return;
    int beg = g_rowptr[w], end = g_rowptr[w + 1];
    float a0 = 0.f, a1 = 0.f, a2 = 0.f, a3 = 0.f;
    int j = beg;
    for (; j + 8 <= end; j += 8) {
        uint2 u[8];
        #pragma unroll
        for (int q = 0; q < 8; ++q) {
            int s = g_col[j + q];
            u[q] = *((const uint2*)(yl + (size_t)s * D) + lane);
        }
        #pragma unroll
        for (int q = 0; q < 8; ++q) {
            float2 f0 = __half22float2(*(__half2*)&u[q].x);
            float2 f1 = __half22float2(*(__half2*)&u[q].y);
            a0 += f0.x; a1 += f0.y; a2 += f1.x; a3 += f1.y;
        }
    }
    for (; j < end; ++j) {
        int s = g_col[j];
        uint2 u = *((const uint2*)(yl + (size_t)s * D) + lane);
        float2 f0 = __half22float2(*(__half2*)&u.x);
        float2 f1 = __half22float2(*(__half2*)&u.y);
        a0 += f0.x; a1 += f0.y; a2 += f1.x; a3 += f1.y;
    }
    int deg = end - beg;
    float inv = 1.0f / (float)(deg > 1 ? deg : 1);
    uint2 zu = *((const uint2*)(z + (size_t)w * D) + lane);
    float2 z0 = __half22float2(*(__half2*)&zu.x);
    float2 z1 = __half22float2(*(__half2*)&zu.y);
    float v0 = a0 * inv + z0.x, v1 = a1 * inv + z0.y;
    float v2 = a2 * inv + z1.x, v3 = a3 * inv + z1.y;
    if (relu) {
        v0 = v0 > 0.f ? v0 : 0.f; v1 = v1 > 0.f ? v1 : 0.f;
        v2 = v2 > 0.f ? v2 : 0.f; v3 = v3 > 0.f ? v3 : 0.f;
    }
    if (outh) {
        *((uint2*)(outh + (size_t)w * D) + lane) =
            make_uint2(pack2(__float2half_rn(v0), __float2half_rn(v1)),
                       pack2(__float2half_rn(v2), __float2half_rn(v3)));
    } else {
        *((float4*)(outf + (size_t)w * D) + lane) = make_float4(v0, v1, v2, v3);
    }
}

// ---------------- launch ----------------
extern "C" void kernel_launch(void* const* d_in, const int* in_sizes, int n_in,
                              void* d_out, int out_size)
{
    const float* x   = (const float*)d_in[0];
    const int*   ei  = (const int*)d_in[1];
    const float* W1l = (const float*)d_in[2];
    const float* b1  = (const float*)d_in[3];
    const float* W1r = (const float*)d_in[4];
    const float* W2l = (const float*)d_in[5];
    const float* b2  = (const float*)d_in[6];
    const float* W2r = (const float*)d_in[7];
    float* out = (float*)d_out;

    int N = in_sizes[0] / D;
    int E = in_sizes[1] / 2;
    const int* src = ei;
    const int* dst = ei + E;

    __half *hh, *yl, *z;
    u32 *B0, *B1, *B2, *B3;
    cudaGetSymbolAddress((void**)&hh, g_hh);
    cudaGetSymbolAddress((void**)&yl, g_yl);
    cudaGetSymbolAddress((void**)&z,  g_z);
    {
        u32* bb;
        cudaGetSymbolAddress((void**)&bb, g_B);
        B0 = bb; B1 = bb + 8192; B2 = bb + 16384; B3 = bb + 24576;
    }

    cudaFuncSetAttribute(k_gemm, cudaFuncAttributeMaxDynamicSharedMemorySize,
                         SM_U32_TOTAL * 4);

    static cudaStream_t sB = nullptr;
    static cudaEvent_t evFork = nullptr, evJoin = nullptr;
    if (!sB) {
        cudaStreamCreateWithFlags(&sB, cudaStreamNonBlocking);
        cudaEventCreateWithFlags(&evFork, cudaEventDisableTiming);
        cudaEventCreateWithFlags(&evJoin, cudaEventDisableTiming);
    }

    int e4 = (E + 3) / 4;
    int nb = (N + 1023) / 1024;
    int aggBlocks  = (N * 32 + 255) / 256;
    int gemmBlocks = (N + 127) / 128;

    // fork: CSR build on side stream (rank-based, single atomic pass, no zero pass)
    cudaEventRecord(evFork, 0);
    cudaStreamWaitEvent(sB, evFork, 0);
    k_hist   <<<(e4 + 255) / 256, 256, 0, sB>>>(dst, e4);
    k_scanLB <<<nb, 1024, 0, sB>>>(N, E);
    k_scatter<<<(e4 + 255) / 256, 256, 0, sB>>>(src, dst, e4);
    cudaEventRecord(evJoin, sB);

    // main stream: weights + layer-1 GEMM (reads fp32 x directly)
    k_prepB<<<4, 256>>>(W1l, W1r, W2l, W2r);
    k_gemm <<<gemmBlocks, 256, SM_U32_TOTAL * 4>>>(
        x, nullptr, 1, B0, B1, b1, yl, z, N);

    // join, then agg/gemm/agg
    cudaStreamWaitEvent(0, evJoin, 0);
    k_aggf<<<aggBlocks, 256>>>(yl, z, hh, nullptr, 1, N);
    k_gemm<<<gemmBlocks, 256, SM_U32_TOTAL * 4>>>(
        nullptr, hh, 0, B2, B3, b2, yl, z, N);
    k_aggf<<<aggBlocks, 256>>>(yl, z, nullptr, out, 0, N);
}

// round 16
// speedup vs baseline: 1.1852x; 1.0400x over previous
#include <cuda_runtime.h>
#include <cuda_fp16.h>
#include <cstdint>

#define NN 100000
#define NE 1600000
#define D  128
#define NPAD (NN + 128)

typedef unsigned int u32;
typedef unsigned long long u64;

// ---- scratch (static device globals; allocation-free) ----
// g_cursor/g_bstate are zero at module load; kernels restore them to zero
// each run so graph replays are deterministic without a dedicated zero pass.
__device__ int    g_rowptr[NN + 1];
__device__ int    g_cursor[NN];
__device__ int    g_col[NE];
__device__ int    g_rank[NE];
__device__ u64    g_bstate[128];
__device__ __align__(16) __half g_hh[(size_t)NPAD * D];   // h (fp16)
__device__ __align__(16) __half g_yl[(size_t)NPAD * D];   // A@W_l (fp16)
__device__ __align__(16) __half g_z [(size_t)NPAD * D];   // A@W_r + b (fp16)
__device__ __align__(16) u32 g_B[4][64 * 128];            // fp16 weights k-pair packed

// ---------------- helpers ----------------
__device__ __forceinline__ u32 pack2(__half a, __half b) {
    __half2 h = __halves2half2(a, b);
    return *(u32*)&h;
}
__device__ __forceinline__ void mma16816(float* c, const u32* a, const u32* b) {
    asm volatile(
        "mma.sync.aligned.m16n8k16.row.col.f32.f16.f16.f32 "
        "{%0,%1,%2,%3}, {%4,%5,%6,%7}, {%8,%9}, {%0,%1,%2,%3};"
        : "+f"(c[0]), "+f"(c[1]), "+f"(c[2]), "+f"(c[3])
        : "r"(a[0]), "r"(a[1]), "r"(a[2]), "r"(a[3]), "r"(b[0]), "r"(b[1]));
}

// ---------------- CSR build ----------------
// count + record per-edge rank within its destination bucket.
// Also zeroes g_bstate for the scan (runs before k_scanLB in stream order).
__global__ void k_hist(const int* __restrict__ dst, int e4) {
    int i = blockIdx.x * blockDim.x + threadIdx.x;
    if (i < 128) g_bstate[i] = 0ULL;
    if (i >= e4) return;
    int4 d = ((const int4*)dst)[i];
    int r0 = atomicAdd(&g_cursor[d.x], 1);
    int r1 = atomicAdd(&g_cursor[d.y], 1);
    int r2 = atomicAdd(&g_cursor[d.z], 1);
    int r3 = atomicAdd(&g_cursor[d.w], 1);
    ((int4*)g_rank)[i] = make_int4(r0, r1, r2, r3);
}
// single-pass decoupled-lookback scan: counts -> rowptr (exclusive).
// Restores cursor[i]=0 after consuming it (same thread, after the read).
__global__ void k_scanLB(int n, int e) {
    __shared__ int sh[1024];
    __shared__ int s_T;
    __shared__ int s_prefix;
    int bid = blockIdx.x, t = threadIdx.x;
    int i = bid * 1024 + t;
    int v = (i < n) ? g_cursor[i] : 0;
    sh[t] = v;
    __syncthreads();
    for (int off = 1; off < 1024; off <<= 1) {
        int w = (t >= off) ? sh[t - off] : 0;
        __syncthreads();
        sh[t] += w;
        __syncthreads();
    }
    if (t == 1023) s_T = sh[1023];
    if (t == 0 && bid == 0) s_prefix = 0;
    __syncthreads();
    int T = s_T;

    if (t == 0) {
        u64 st = ((u64)(unsigned)T << 32) | (bid == 0 ? 2ULL : 1ULL);
        atomicExch(&g_bstate[bid], st);
    }
    if (t < 32 && bid > 0) {
        int lane = t;
        int prefix = 0;
        int base = bid - 1;
        while (true) {
            int j = base - lane;
            u64 s = (j >= 0) ? *(volatile u64*)&g_bstate[j] : 2ULL;
            unsigned f = (unsigned)(s & 3ULL);
            if (__all_sync(0xFFFFFFFFu, f != 0u)) {
                int val = (int)(unsigned)(s >> 32);
                unsigned pm = __ballot_sync(0xFFFFFFFFu, f == 2u);
                if (pm) {
                    int fp = __ffs(pm) - 1;
                    int xx = (lane <= fp) ? val : 0;
                    #pragma unroll
                    for (int o = 16; o; o >>= 1) xx += __shfl_xor_sync(0xFFFFFFFFu, xx, o);
                    prefix += xx;
                    break;
                } else {
                    int xx = val;
                    #pragma unroll
                    for (int o = 16; o; o >>= 1) xx += __shfl_xor_sync(0xFFFFFFFFu, xx, o);
                    prefix += xx;
                    base -= 32;
                }
            }
        }
        if (lane == 0) {
            atomicExch(&g_bstate[bid], ((u64)(unsigned)(prefix + T) << 32) | 2ULL);
            s_prefix = prefix;
        }
    }
    __syncthreads();
    int r = s_prefix + sh[t] - v;
    if (i < n) {
        g_rowptr[i] = r;
        g_cursor[i] = 0;          // restore for next graph replay
    }
    if (bid == 0 && t == 0) g_rowptr[n] = e;
}
// atomic-free scatter: position = rowptr[dst] + rank
__global__ void k_scatter(const int* __restrict__ src, const int* __restrict__ dst, int e4) {
    int i = blockIdx.x * blockDim.x + threadIdx.x;
    if (i >= e4) return;
    int4 s = ((const int4*)src)[i];
    int4 d = ((const int4*)dst)[i];
    int4 r = ((const int4*)g_rank)[i];
    int p0 = g_rowptr[d.x] + r.x;
    int p1 = g_rowptr[d.y] + r.y;
    int p2 = g_rowptr[d.z] + r.z;
    int p3 = g_rowptr[d.w] + r.w;
    g_col[p0] = s.x;
    g_col[p1] = s.y;
    g_col[p2] = s.z;
    g_col[p3] = s.w;
}

// ---------------- weight prep: fp32 W[k][n] -> fp16 k-pair-packed [kp][n] ----------------
// 128 CTAs: blockIdx.x>>5 selects weight, low 5 bits select the 256-element chunk.
// One packed u32 output per thread (2 coalesced float loads).
__global__ void k_prepB(const float* __restrict__ W0, const float* __restrict__ W1,
                        const float* __restrict__ W2, const float* __restrict__ W3) {
    const float* Ws[4] = {W0, W1, W2, W3};
    int widx = blockIdx.x >> 5;
    const float* W = Ws[widx];
    u32* b = g_B[widx];
    int u = (blockIdx.x & 31) * 256 + threadIdx.x;   // 0..8191
    int kp = u >> 7, n = u & 127;
    b[u] = pack2(__float2half_rn(W[(2 * kp) * D + n]),
                 __float2half_rn(W[(2 * kp + 1) * D + n]));
}

// ---------------- HMMA cat-GEMM: [yl | z] = A @ [Bl | Br] (+bias on z) ----------------
#define AS 68
#define BS 264
#define SM_U32_TOTAL (128 * AS + 64 * BS)

__global__ __launch_bounds__(256, 1) void k_gemm(
    const float* __restrict__ A32, const __half* __restrict__ A16, int a32,
    const u32* __restrict__ Bg0, const u32* __restrict__ Bg1,
    const float* __restrict__ bias,
    __half* __restrict__ yl, __half* __restrict__ z, int M)
{
    extern __shared__ __align__(16) u32 sm[];
    u32* Asm = sm;
    u32* Bsm = sm + 128 * AS;

    int tid = threadIdx.x, wid = tid >> 5, lane = tid & 31;
    int g = lane >> 2, tg = lane & 3;
    int wm = (wid & 1) * 64, wn = (wid >> 1) * 64;
    int m0 = blockIdx.x * 128;

    for (int u = tid; u < 2048; u += 256) {
        int r = u >> 5, c4 = u & 31;
        *(uint4*)&Bsm[r * BS + c4 * 4]       = ((const uint4*)Bg0)[u];
        *(uint4*)&Bsm[r * BS + 128 + c4 * 4] = ((const uint4*)Bg1)[u];
    }
    if (a32) {
        for (int u = tid; u < 2048; u += 256) {
            int r = u >> 4, c4 = u & 15;
            int gr = m0 + r;
            float4 fa = make_float4(0.f, 0.f, 0.f, 0.f), fb = fa;
            if (gr < M) {
                const float4* p = (const float4*)(A32 + (size_t)gr * D + c4 * 8);
                fa = p[0]; fb = p[1];
            }
            *(uint4*)&Asm[r * AS + c4 * 4] = make_uint4(
                pack2(__float2half_rn(fa.x), __float2half_rn(fa.y)),
                pack2(__float2half_rn(fa.z), __float2half_rn(fa.w)),
                pack2(__float2half_rn(fb.x), __float2half_rn(fb.y)),
                pack2(__float2half_rn(fb.z), __float2half_rn(fb.w)));
        }
    } else {
        const u32* Ag = (const u32*)A16;
        for (int u = tid; u < 2048; u += 256) {
            int r = u >> 4, c4 = u & 15;
            *(uint4*)&Asm[r * AS + c4 * 4] =
                *(const uint4*)(Ag + (size_t)(m0 + r) * 64 + c4 * 4);
        }
    }
    __syncthreads();

    float acc[4][8][4];
    #pragma unroll
    for (int mt = 0; mt < 4; ++mt)
        #pragma unroll
        for (int nt = 0; nt < 8; ++nt)
            #pragma unroll
            for (int c = 0; c < 4; ++c) acc[mt][nt][c] = 0.f;

    #pragma unroll
    for (int ks = 0; ks < 8; ++ks) {
        u32 afr[4][4];
        #pragma unroll
        for (int mt = 0; mt < 4; ++mt) {
            int r = wm + mt * 16 + g;
            afr[mt][0] = Asm[r * AS + ks * 8 + tg];
            afr[mt][1] = Asm[(r + 8) * AS + ks * 8 + tg];
            afr[mt][2] = Asm[r * AS + ks * 8 + tg + 4];
            afr[mt][3] = Asm[(r + 8) * AS + ks * 8 + tg + 4];
        }
        u32 bfr[8][2];
        #pragma unroll
        for (int nt = 0; nt < 8; ++nt) {
            int n = wn + nt * 8 + g;
            bfr[nt][0] = Bsm[(ks * 8 + tg) * BS + n];
            bfr[nt][1] = Bsm[(ks * 8 + tg + 4) * BS + n];
        }
        #pragma unroll
        for (int mt = 0; mt < 4; ++mt)
            #pragma unroll
            for (int nt = 0; nt < 8; ++nt)
                mma16816(acc[mt][nt], afr[mt], bfr[nt]);
    }

    #pragma unroll
    for (int nt = 0; nt < 8; ++nt) {
        int ccol = wn + nt * 8 + tg * 2;
        if (ccol < 128) {
            #pragma unroll
            for (int mt = 0; mt < 4; ++mt) {
                int r0 = m0 + wm + mt * 16 + g;
                *(__half2*)(yl + (size_t)r0 * D + ccol) =
                    __floats2half2_rn(acc[mt][nt][0], acc[mt][nt][1]);
                *(__half2*)(yl + (size_t)(r0 + 8) * D + ccol) =
                    __floats2half2_rn(acc[mt][nt][2], acc[mt][nt][3]);
            }
        } else {
            int zc = ccol - 128;
            float bv0 = __ldg(bias + zc), bv1 = __ldg(bias + zc + 1);
            #pragma unroll
            for (int mt = 0; mt < 4; ++mt) {
                int r0 = m0 + wm + mt * 16 + g;
                *(__half2*)(z + (size_t)r0 * D + zc) =
                    __floats2half2_rn(acc[mt][nt][0] + bv0, acc[mt][nt][1] + bv1);
                *(__half2*)(z + (size_t)(r0 + 8) * D + zc) =
                    __floats2half2_rn(acc[mt][nt][2] + bv0, acc[mt][nt][3] + bv1);
            }
        }
    }
}

// ---------------- fused mean-agg + add-self + (relu) ----------------
__global__ void k_aggf(const __half* __restrict__ yl, const __half* __restrict__ z,
                       __half* __restrict__ outh, float* __restrict__ outf,
                       int relu, int n)
{
    int w    = (blockIdx.x * blockDim.x + threadIdx.x) >> 5;
    int lane = threadIdx.x & 31;
    if (w >= n) return;
    int beg = g_rowptr[w], end = g_rowptr[w + 1];
    float a0 = 0.f, a1 = 0.f, a2 = 0.f, a3 = 0.f;
    int j = beg;
    for (; j + 8 <= end; j += 8) {
        uint2 u[8];
        #pragma unroll
        for (int q = 0; q < 8; ++q) {
            int s = g_col[j + q];
            u[q] = *((const uint2*)(yl + (size_t)s * D) + lane);
        }
        #pragma unroll
        for (int q = 0; q < 8; ++q) {
            float2 f0 = __half22float2(*(__half2*)&u[q].x);
            float2 f1 = __half22float2(*(__half2*)&u[q].y);
            a0 += f0.x; a1 += f0.y; a2 += f1.x; a3 += f1.y;
        }
    }
    for (; j < end; ++j) {
        int s = g_col[j];
        uint2 u = *((const uint2*)(yl + (size_t)s * D) + lane);
        float2 f0 = __half22float2(*(__half2*)&u.x);
        float2 f1 = __half22float2(*(__half2*)&u.y);
        a0 += f0.x; a1 += f0.y; a2 += f1.x; a3 += f1.y;
    }
    int deg = end - beg;
    float inv = 1.0f / (float)(deg > 1 ? deg : 1);
    uint2 zu = *((const uint2*)(z + (size_t)w * D) + lane);
    float2 z0 = __half22float2(*(__half2*)&zu.x);
    float2 z1 = __half22float2(*(__half2*)&zu.y);
    float v0 = a0 * inv + z0.x, v1 = a1 * inv + z0.y;
    float v2 = a2 * inv + z1.x, v3 = a3 * inv + z1.y;
    if (relu) {
        v0 = v0 > 0.f ? v0 : 0.f; v1 = v1 > 0.f ? v1 : 0.f;
        v2 = v2 > 0.f ? v2 : 0.f; v3 = v3 > 0.f ? v3 : 0.f;
    }
    if (outh) {
        *((uint2*)(outh + (size_t)w * D) + lane) =
            make_uint2(pack2(__float2half_rn(v0), __float2half_rn(v1)),
                       pack2(__float2half_rn(v2), __float2half_rn(v3)));
    } else {
        *((float4*)(outf + (size_t)w * D) + lane) = make_float4(v0, v1, v2, v3);
    }
}

// ---------------- launch ----------------
extern "C" void kernel_launch(void* const* d_in, const int* in_sizes, int n_in,
                              void* d_out, int out_size)
{
    const float* x   = (const float*)d_in[0];
    const int*   ei  = (const int*)d_in[1];
    const float* W1l = (const float*)d_in[2];
    const float* b1  = (const float*)d_in[3];
    const float* W1r = (const float*)d_in[4];
    const float* W2l = (const float*)d_in[5];
    const float* b2  = (const float*)d_in[6];
    const float* W2r = (const float*)d_in[7];
    float* out = (float*)d_out;

    int N = in_sizes[0] / D;
    int E = in_sizes[1] / 2;
    const int* src = ei;
    const int* dst = ei + E;

    __half *hh, *yl, *z;
    u32 *B0, *B1, *B2, *B3;
    cudaGetSymbolAddress((void**)&hh, g_hh);
    cudaGetSymbolAddress((void**)&yl, g_yl);
    cudaGetSymbolAddress((void**)&z,  g_z);
    {
        u32* bb;
        cudaGetSymbolAddress((void**)&bb, g_B);
        B0 = bb; B1 = bb + 8192; B2 = bb + 16384; B3 = bb + 24576;
    }

    cudaFuncSetAttribute(k_gemm, cudaFuncAttributeMaxDynamicSharedMemorySize,
                         SM_U32_TOTAL * 4);

    static cudaStream_t sB = nullptr;
    static cudaEvent_t evFork = nullptr, evJoin = nullptr;
    if (!sB) {
        cudaStreamCreateWithFlags(&sB, cudaStreamNonBlocking);
        cudaEventCreateWithFlags(&evFork, cudaEventDisableTiming);
        cudaEventCreateWithFlags(&evJoin, cudaEventDisableTiming);
    }

    int e4 = (E + 3) / 4;
    int nb = (N + 1023) / 1024;
    int aggBlocks  = (N * 32 + 255) / 256;
    int gemmBlocks = (N + 127) / 128;

    // fork: CSR build on side stream (rank-based, single atomic pass, no zero pass)
    cudaEventRecord(evFork, 0);
    cudaStreamWaitEvent(sB, evFork, 0);
    k_hist   <<<(e4 + 255) / 256, 256, 0, sB>>>(dst, e4);
    k_scanLB <<<nb, 1024, 0, sB>>>(N, E);
    k_scatter<<<(e4 + 255) / 256, 256, 0, sB>>>(src, dst, e4);
    cudaEventRecord(evJoin, sB);

    // main stream: weights + layer-1 GEMM (reads fp32 x directly)
    k_prepB<<<128, 256>>>(W1l, W1r, W2l, W2r);
    k_gemm <<<gemmBlocks, 256, SM_U32_TOTAL * 4>>>(
        x, nullptr, 1, B0, B1, b1, yl, z, N);

    // join, then agg/gemm/agg
    cudaStreamWaitEvent(0, evJoin, 0);
    k_aggf<<<aggBlocks, 256>>>(yl, z, hh, nullptr, 1, N);
    k_gemm<<<gemmBlocks, 256, SM_U32_TOTAL * 4>>>(
        nullptr, hh, 0, B2, B3, b2, yl, z, N);
    k_aggf<<<aggBlocks, 256>>>(yl, z, nullptr, out, 0, N);
}

// round 17
// speedup vs baseline: 1.1921x; 1.0058x over previous
#include <cuda_runtime.h>
#include <cuda_fp16.h>
#include <cstdint>

#define NN 100000
#define NE 1600000
#define D  128
#define NPAD (NN + 128)

typedef unsigned int u32;
typedef unsigned long long u64;

// ---- scratch (static device globals; allocation-free) ----
// g_cursor/g_bstate are zero at module load; kernels restore them to zero
// each run so graph replays are deterministic without a dedicated zero pass.
__device__ int    g_rowptr[NN + 1];
__device__ int    g_cursor[NN];
__device__ int    g_col[NE];
__device__ int    g_rank[NE];
__device__ u64    g_bstate[128];
__device__ __align__(16) __half g_hh[(size_t)NPAD * D];   // h (fp16)
__device__ __align__(16) __half g_yl[(size_t)NPAD * D];   // A@W_l (fp16)
__device__ __align__(16) __half g_z [(size_t)NPAD * D];   // A@W_r + b (fp16)
__device__ __align__(16) u32 g_B[4][64 * 128];            // fp16 weights k-pair packed

// ---------------- helpers ----------------
__device__ __forceinline__ u32 pack2(__half a, __half b) {
    __half2 h = __halves2half2(a, b);
    return *(u32*)&h;
}
__device__ __forceinline__ void mma16816(float* c, const u32* a, const u32* b) {
    asm volatile(
        "mma.sync.aligned.m16n8k16.row.col.f32.f16.f16.f32 "
        "{%0,%1,%2,%3}, {%4,%5,%6,%7}, {%8,%9}, {%0,%1,%2,%3};"
        : "+f"(c[0]), "+f"(c[1]), "+f"(c[2]), "+f"(c[3])
        : "r"(a[0]), "r"(a[1]), "r"(a[2]), "r"(a[3]), "r"(b[0]), "r"(b[1]));
}

// ---------------- CSR build ----------------
// 8 edges/thread: count + record per-edge rank within its destination bucket.
// Also zeroes g_bstate for the scan (runs before k_scanLB in stream order).
__global__ void k_hist(const int* __restrict__ dst, int e8, int E) {
    int i = blockIdx.x * blockDim.x + threadIdx.x;
    if (i < 128) g_bstate[i] = 0ULL;
    if (i >= e8) return;
    int base = i * 8;
    if (base + 8 <= E) {
        int4 da = *(const int4*)(dst + base);
        int4 db = *(const int4*)(dst + base + 4);
        int r0 = atomicAdd(&g_cursor[da.x], 1);
        int r1 = atomicAdd(&g_cursor[da.y], 1);
        int r2 = atomicAdd(&g_cursor[da.z], 1);
        int r3 = atomicAdd(&g_cursor[da.w], 1);
        int r4 = atomicAdd(&g_cursor[db.x], 1);
        int r5 = atomicAdd(&g_cursor[db.y], 1);
        int r6 = atomicAdd(&g_cursor[db.z], 1);
        int r7 = atomicAdd(&g_cursor[db.w], 1);
        *(int4*)(g_rank + base)     = make_int4(r0, r1, r2, r3);
        *(int4*)(g_rank + base + 4) = make_int4(r4, r5, r6, r7);
    } else {
        for (int k = base; k < E; ++k)
            g_rank[k] = atomicAdd(&g_cursor[dst[k]], 1);
    }
}
// single-pass decoupled-lookback scan: counts -> rowptr (exclusive).
// Restores cursor[i]=0 after consuming it (same thread, after the read).
__global__ void k_scanLB(int n, int e) {
    __shared__ int sh[1024];
    __shared__ int s_T;
    __shared__ int s_prefix;
    int bid = blockIdx.x, t = threadIdx.x;
    int i = bid * 1024 + t;
    int v = (i < n) ? g_cursor[i] : 0;
    sh[t] = v;
    __syncthreads();
    for (int off = 1; off < 1024; off <<= 1) {
        int w = (t >= off) ? sh[t - off] : 0;
        __syncthreads();
        sh[t] += w;
        __syncthreads();
    }
    if (t == 1023) s_T = sh[1023];
    if (t == 0 && bid == 0) s_prefix = 0;
    __syncthreads();
    int T = s_T;

    if (t == 0) {
        u64 st = ((u64)(unsigned)T << 32) | (bid == 0 ? 2ULL : 1ULL);
        atomicExch(&g_bstate[bid], st);
    }
    if (t < 32 && bid > 0) {
        int lane = t;
        int prefix = 0;
        int base = bid - 1;
        while (true) {
            int j = base - lane;
            u64 s = (j >= 0) ? *(volatile u64*)&g_bstate[j] : 2ULL;
            unsigned f = (unsigned)(s & 3ULL);
            if (__all_sync(0xFFFFFFFFu, f != 0u)) {
                int val = (int)(unsigned)(s >> 32);
                unsigned pm = __ballot_sync(0xFFFFFFFFu, f == 2u);
                if (pm) {
                    int fp = __ffs(pm) - 1;
                    int xx = (lane <= fp) ? val : 0;
                    #pragma unroll
                    for (int o = 16; o; o >>= 1) xx += __shfl_xor_sync(0xFFFFFFFFu, xx, o);
                    prefix += xx;
                    break;
                } else {
                    int xx = val;
                    #pragma unroll
                    for (int o = 16; o; o >>= 1) xx += __shfl_xor_sync(0xFFFFFFFFu, xx, o);
                    prefix += xx;
                    base -= 32;
                }
            }
        }
        if (lane == 0) {
            atomicExch(&g_bstate[bid], ((u64)(unsigned)(prefix + T) << 32) | 2ULL);
            s_prefix = prefix;
        }
    }
    __syncthreads();
    int r = s_prefix + sh[t] - v;
    if (i < n) {
        g_rowptr[i] = r;
        g_cursor[i] = 0;          // restore for next graph replay
    }
    if (bid == 0 && t == 0) g_rowptr[n] = e;
}
// atomic-free scatter, 8 edges/thread: position = rowptr[dst] + rank
__global__ void k_scatter(const int* __restrict__ src, const int* __restrict__ dst,
                          int e8, int E) {
    int i = blockIdx.x * blockDim.x + threadIdx.x;
    if (i >= e8) return;
    int base = i * 8;
    if (base + 8 <= E) {
        int4 sa = *(const int4*)(src + base);
        int4 sb = *(const int4*)(src + base + 4);
        int4 da = *(const int4*)(dst + base);
        int4 db = *(const int4*)(dst + base + 4);
        int4 ra = *(const int4*)(g_rank + base);
        int4 rb = *(const int4*)(g_rank + base + 4);
        int p0 = g_rowptr[da.x] + ra.x;
        int p1 = g_rowptr[da.y] + ra.y;
        int p2 = g_rowptr[da.z] + ra.z;
        int p3 = g_rowptr[da.w] + ra.w;
        int p4 = g_rowptr[db.x] + rb.x;
        int p5 = g_rowptr[db.y] + rb.y;
        int p6 = g_rowptr[db.z] + rb.z;
        int p7 = g_rowptr[db.w] + rb.w;
        g_col[p0] = sa.x; g_col[p1] = sa.y; g_col[p2] = sa.z; g_col[p3] = sa.w;
        g_col[p4] = sb.x; g_col[p5] = sb.y; g_col[p6] = sb.z; g_col[p7] = sb.w;
    } else {
        for (int k = base; k < E; ++k)
            g_col[g_rowptr[dst[k]] + g_rank[k]] = src[k];
    }
}

// ---------------- weight prep: fp32 W[k][n] -> fp16 k-pair-packed [kp][n] ----------------
// 128 CTAs: blockIdx.x>>5 selects weight, low 5 bits select the 256-element chunk.
__global__ void k_prepB(const float* __restrict__ W0, const float* __restrict__ W1,
                        const float* __restrict__ W2, const float* __restrict__ W3) {
    const float* Ws[4] = {W0, W1, W2, W3};
    int widx = blockIdx.x >> 5;
    const float* W = Ws[widx];
    u32* b = g_B[widx];
    int u = (blockIdx.x & 31) * 256 + threadIdx.x;   // 0..8191
    int kp = u >> 7, n = u & 127;
    b[u] = pack2(__float2half_rn(W[(2 * kp) * D + n]),
                 __float2half_rn(W[(2 * kp + 1) * D + n]));
}

// ---------------- HMMA cat-GEMM: [yl | z] = A @ [Bl | Br] (+bias on z) ----------------
#define AS 68
#define BS 264
#define SM_U32_TOTAL (128 * AS + 64 * BS)

__global__ __launch_bounds__(256, 1) void k_gemm(
    const float* __restrict__ A32, const __half* __restrict__ A16, int a32,
    const u32* __restrict__ Bg0, const u32* __restrict__ Bg1,
    const float* __restrict__ bias,
    __half* __restrict__ yl, __half* __restrict__ z, int M)
{
    extern __shared__ __align__(16) u32 sm[];
    u32* Asm = sm;
    u32* Bsm = sm + 128 * AS;

    int tid = threadIdx.x, wid = tid >> 5, lane = tid & 31;
    int g = lane >> 2, tg = lane & 3;
    int wm = (wid & 1) * 64, wn = (wid >> 1) * 64;
    int m0 = blockIdx.x * 128;

    for (int u = tid; u < 2048; u += 256) {
        int r = u >> 5, c4 = u & 31;
        *(uint4*)&Bsm[r * BS + c4 * 4]       = ((const uint4*)Bg0)[u];
        *(uint4*)&Bsm[r * BS + 128 + c4 * 4] = ((const uint4*)Bg1)[u];
    }
    if (a32) {
        for (int u = tid; u < 2048; u += 256) {
            int r = u >> 4, c4 = u & 15;
            int gr = m0 + r;
            float4 fa = make_float4(0.f, 0.f, 0.f, 0.f), fb = fa;
            if (gr < M) {
                const float4* p = (const float4*)(A32 + (size_t)gr * D + c4 * 8);
                fa = p[0]; fb = p[1];
            }
            *(uint4*)&Asm[r * AS + c4 * 4] = make_uint4(
                pack2(__float2half_rn(fa.x), __float2half_rn(fa.y)),
                pack2(__float2half_rn(fa.z), __float2half_rn(fa.w)),
                pack2(__float2half_rn(fb.x), __float2half_rn(fb.y)),
                pack2(__float2half_rn(fb.z), __float2half_rn(fb.w)));
        }
    } else {
        const u32* Ag = (const u32*)A16;
        for (int u = tid; u < 2048; u += 256) {
            int r = u >> 4, c4 = u & 15;
            *(uint4*)&Asm[r * AS + c4 * 4] =
                *(const uint4*)(Ag + (size_t)(m0 + r) * 64 + c4 * 4);
        }
    }
    __syncthreads();

    float acc[4][8][4];
    #pragma unroll
    for (int mt = 0; mt < 4; ++mt)
        #pragma unroll
        for (int nt = 0; nt < 8; ++nt)
            #pragma unroll
            for (int c = 0; c < 4; ++c) acc[mt][nt][c] = 0.f;

    #pragma unroll
    for (int ks = 0; ks < 8; ++ks) {
        u32 afr[4][4];
        #pragma unroll
        for (int mt = 0; mt < 4; ++mt) {
            int r = wm + mt * 16 + g;
            afr[mt][0] = Asm[r * AS + ks * 8 + tg];
            afr[mt][1] = Asm[(r + 8) * AS + ks * 8 + tg];
            afr[mt][2] = Asm[r * AS + ks * 8 + tg + 4];
            afr[mt][3] = Asm[(r + 8) * AS + ks * 8 + tg + 4];
        }
        u32 bfr[8][2];
        #pragma unroll
        for (int nt = 0; nt < 8; ++nt) {
            int n = wn + nt * 8 + g;
            bfr[nt][0] = Bsm[(ks * 8 + tg) * BS + n];
            bfr[nt][1] = Bsm[(ks * 8 + tg + 4) * BS + n];
        }
        #pragma unroll
        for (int mt = 0; mt < 4; ++mt)
            #pragma unroll
            for (int nt = 0; nt < 8; ++nt)
                mma16816(acc[mt][nt], afr[mt], bfr[nt]);
    }

    #pragma unroll
    for (int nt = 0; nt < 8; ++nt) {
        int ccol = wn + nt * 8 + tg * 2;
        if (ccol < 128) {
            #pragma unroll
            for (int mt = 0; mt < 4; ++mt) {
                int r0 = m0 + wm + mt * 16 + g;
                *(__half2*)(yl + (size_t)r0 * D + ccol) =
                    __floats2half2_rn(acc[mt][nt][0], acc[mt][nt][1]);
                *(__half2*)(yl + (size_t)(r0 + 8) * D + ccol) =
                    __floats2half2_rn(acc[mt][nt][2], acc[mt][nt][3]);
            }
        } else {
            int zc = ccol - 128;
            float bv0 = __ldg(bias + zc), bv1 = __ldg(bias + zc + 1);
            #pragma unroll
            for (int mt = 0; mt < 4; ++mt) {
                int r0 = m0 + wm + mt * 16 + g;
                *(__half2*)(z + (size_t)r0 * D + zc) =
                    __floats2half2_rn(acc[mt][nt][0] + bv0, acc[mt][nt][1] + bv1);
                *(__half2*)(z + (size_t)(r0 + 8) * D + zc) =
                    __floats2half2_rn(acc[mt][nt][2] + bv0, acc[mt][nt][3] + bv1);
            }
        }
    }
}

// ---------------- fused mean-agg + add-self + (relu) ----------------
__global__ void k_aggf(const __half* __restrict__ yl, const __half* __restrict__ z,
                       __half* __restrict__ outh, float* __restrict__ outf,
                       int relu, int n)
{
    int w    = (blockIdx.x * blockDim.x + threadIdx.x) >> 5;
    int lane = threadIdx.x & 31;
    if (w >= n) return;
    int beg = g_rowptr[w], end = g_rowptr[w + 1];
    float a0 = 0.f, a1 = 0.f, a2 = 0.f, a3 = 0.f;
    int j = beg;
    for (; j + 8 <= end; j += 8) {
        uint2 u[8];
        #pragma unroll
        for (int q = 0; q < 8; ++q) {
            int s = g_col[j + q];
            u[q] = *((const uint2*)(yl + (size_t)s * D) + lane);
        }
        #pragma unroll
        for (int q = 0; q < 8; ++q) {
            float2 f0 = __half22float2(*(__half2*)&u[q].x);
            float2 f1 = __half22float2(*(__half2*)&u[q].y);
            a0 += f0.x; a1 += f0.y; a2 += f1.x; a3 += f1.y;
        }
    }
    for (; j < end; ++j) {
        int s = g_col[j];
        uint2 u = *((const uint2*)(yl + (size_t)s * D) + lane);
        float2 f0 = __half22float2(*(__half2*)&u.x);
        float2 f1 = __half22float2(*(__half2*)&u.y);
        a0 += f0.x; a1 += f0.y; a2 += f1.x; a3 += f1.y;
    }
    int deg = end - beg;
    float inv = 1.0f / (float)(deg > 1 ? deg : 1);
    uint2 zu = *((const uint2*)(z + (size_t)w * D) + lane);
    float2 z0 = __half22float2(*(__half2*)&zu.x);
    float2 z1 = __half22float2(*(__half2*)&zu.y);
    float v0 = a0 * inv + z0.x, v1 = a1 * inv + z0.y;
    float v2 = a2 * inv + z1.x, v3 = a3 * inv + z1.y;
    if (relu) {
        v0 = v0 > 0.f ? v0 : 0.f; v1 = v1 > 0.f ? v1 : 0.f;
        v2 = v2 > 0.f ? v2 : 0.f; v3 = v3 > 0.f ? v3 : 0.f;
    }
    if (outh) {
        *((uint2*)(outh + (size_t)w * D) + lane) =
            make_uint2(pack2(__float2half_rn(v0), __float2half_rn(v1)),
                       pack2(__float2half_rn(v2), __float2half_rn(v3)));
    } else {
        *((float4*)(outf + (size_t)w * D) + lane) = make_float4(v0, v1, v2, v3);
    }
}

// ---------------- launch ----------------
extern "C" void kernel_launch(void* const* d_in, const int* in_sizes, int n_in,
                              void* d_out, int out_size)
{
    const float* x   = (const float*)d_in[0];
    const int*   ei  = (const int*)d_in[1];
    const float* W1l = (const float*)d_in[2];
    const float* b1  = (const float*)d_in[3];
    const float* W1r = (const float*)d_in[4];
    const float* W2l = (const float*)d_in[5];
    const float* b2  = (const float*)d_in[6];
    const float* W2r = (const float*)d_in[7];
    float* out = (float*)d_out;

    int N = in_sizes[0] / D;
    int E = in_sizes[1] / 2;
    const int* src = ei;
    const int* dst = ei + E;

    __half *hh, *yl, *z;
    u32 *B0, *B1, *B2, *B3;
    cudaGetSymbolAddress((void**)&hh, g_hh);
    cudaGetSymbolAddress((void**)&yl, g_yl);
    cudaGetSymbolAddress((void**)&z,  g_z);
    {
        u32* bb;
        cudaGetSymbolAddress((void**)&bb, g_B);
        B0 = bb; B1 = bb + 8192; B2 = bb + 16384; B3 = bb + 24576;
    }

    cudaFuncSetAttribute(k_gemm, cudaFuncAttributeMaxDynamicSharedMemorySize,
                         SM_U32_TOTAL * 4);

    static cudaStream_t sB = nullptr;
    static cudaEvent_t evFork = nullptr, evJoin = nullptr;
    if (!sB) {
        cudaStreamCreateWithFlags(&sB, cudaStreamNonBlocking);
        cudaEventCreateWithFlags(&evFork, cudaEventDisableTiming);
        cudaEventCreateWithFlags(&evJoin, cudaEventDisableTiming);
    }

    int e8 = (E + 7) / 8;
    int nb = (N + 1023) / 1024;
    int aggBlocks  = (N * 32 + 255) / 256;
    int gemmBlocks = (N + 127) / 128;

    // fork: CSR build on side stream (rank-based, single atomic pass, 8 edges/thread)
    cudaEventRecord(evFork, 0);
    cudaStreamWaitEvent(sB, evFork, 0);
    k_hist   <<<(e8 + 255) / 256, 256, 0, sB>>>(dst, e8, E);
    k_scanLB <<<nb, 1024, 0, sB>>>(N, E);
    k_scatter<<<(e8 + 255) / 256, 256, 0, sB>>>(src, dst, e8, E);
    cudaEventRecord(evJoin, sB);

    // main stream: weights + layer-1 GEMM (reads fp32 x directly)
    k_prepB<<<128, 256>>>(W1l, W1r, W2l, W2r);
    k_gemm <<<gemmBlocks, 256, SM_U32_TOTAL * 4>>>(
        x, nullptr, 1, B0, B1, b1, yl, z, N);

    // join, then agg/gemm/agg
    cudaStreamWaitEvent(0, evJoin, 0);
    k_aggf<<<aggBlocks, 256>>>(yl, z, hh, nullptr, 1, N);
    k_gemm<<<gemmBlocks, 256, SM_U32_TOTAL * 4>>>(
        nullptr, hh, 0, B2, B3, b2, yl, z, N);
    k_aggf<<<aggBlocks, 256>>>(yl, z, nullptr, out, 0, N);
}